// round 5
// baseline (speedup 1.0000x reference)
#include <cuda_runtime.h>
#include <math.h>

#define Bn 16
#define Nn 256
#define Tn 64
#define Wn 12
#define Hn 64
#define EDn 64
#define Sn 5
#define Cn 4
#define En 2048
#define FGn 76   // W + H

// ---------------- device scratch (no allocation allowed) ----------------
__device__ float g_A[Nn * Nn];                 // static adjacency accumulator
__device__ float g_AnT[Nn * Nn];               // normalized static adj, transposed [j][i]
__device__ float g_dinv_stat[Nn];
__device__ float g_coef[6 * Hn];               // az, cz0, ar, cr0, ah, ch0
__device__ float g_XW[Bn * Nn * EDn];
__device__ float g_de1[Bn * Nn * EDn];
__device__ float g_de2[Bn * Nn * EDn];
__device__ float g_Eh[(size_t)Bn * Sn * Nn * Nn];   // ring buffer of Et
__device__ float g_Msum[(size_t)Bn * Nn * Nn];      // running sum over ring slots
__device__ float g_colsum[Bn * Nn];                 // column sums of Msum
__device__ float g_h[Bn * Nn * Hn];

// ---------------- setup kernels ----------------
__global__ void k_zero() {
    size_t idx = (size_t)blockIdx.x * blockDim.x + threadIdx.x;
    size_t str = (size_t)gridDim.x * blockDim.x;
    for (size_t i = idx; i < (size_t)Nn * Nn; i += str) g_A[i] = 0.f;
    for (size_t i = idx; i < (size_t)Bn * Sn * Nn * Nn; i += str) g_Eh[i] = 0.f;
    for (size_t i = idx; i < (size_t)Bn * Nn * Nn; i += str) g_Msum[i] = 0.f;
    for (size_t i = idx; i < (size_t)Bn * Nn; i += str) g_colsum[i] = 0.f;
    for (size_t i = idx; i < (size_t)Bn * Nn * Hn; i += str) g_h[i] = 0.f;
}

__global__ void k_scatter(const int* __restrict__ ei, const float* __restrict__ ew) {
    int e = blockIdx.x * blockDim.x + threadIdx.x;
    if (e < En) atomicAdd(&g_A[ei[e] * Nn + ei[En + e]], ew[e]);
}

__global__ void k_statdeg() {
    int j = threadIdx.x;  // 256 threads, 1 block
    float d = 1.0f;       // self loop
    for (int i = 0; i < Nn; i++) d += g_A[i * Nn + j];
    g_dinv_stat[j] = 1.0f / sqrtf(d);
}

__global__ void k_statAnT() {
    int idx = blockIdx.x * blockDim.x + threadIdx.x;
    if (idx >= Nn * Nn) return;
    int j = idx / Nn, i = idx % Nn;
    float a = g_A[i * Nn + j] + (i == j ? 1.0f : 0.0f);
    g_AnT[idx] = g_dinv_stat[i] * a * g_dinv_stat[j];
}

__global__ void k_precoef(const float* wz_c, const float* wz_l, const float* bz_c,
                          const float* wr_c, const float* wr_l, const float* br_c,
                          const float* wh_c, const float* wh_l, const float* bh_c) {
    int k = threadIdx.x;  // 64 threads
    float az = 0, cz = 0, ar = 0, cr = 0, ah = 0, ch = 0;
    for (int f = 0; f < Hn; f++) {
        float wzl = wz_l[f * Hn + k], wrl = wr_l[f * Hn + k], whl = wh_l[f * Hn + k];
        az += wz_c[f] * wzl;  cz += bz_c[f] * wzl;
        ar += wr_c[f] * wrl;  cr += br_c[f] * wrl;
        ah += wh_c[f] * whl;  ch += bh_c[f] * whl;
    }
    g_coef[k] = az;        g_coef[64 + k] = cz;
    g_coef[128 + k] = ar;  g_coef[192 + k] = cr;
    g_coef[256 + k] = ah;  g_coef[320 + k] = ch;
}

// ---------------- per-step kernel 1: XW = concat(win, h) @ Wg ----------------
__global__ __launch_bounds__(256) void k_xw(const float* __restrict__ x,
                                            const float* __restrict__ Wg, int t) {
    __shared__ float sW[FGn * EDn];     // 76*64
    __shared__ float sIt[16][FGn];
    int tid = threadIdx.x;
    for (int i = tid; i < FGn * EDn; i += 256) sW[i] = Wg[i];
    int row0 = blockIdx.x * 16;
    for (int i = tid; i < 16 * FGn; i += 256) {
        int rr = i / FGn, c = i % FGn;
        int row = row0 + rr;
        float v;
        if (c < Wn) {
            int tt = t + c - (Wn - 1);
            v = (tt >= 0) ? x[row * Tn + tt] : 0.0f;
        } else {
            v = g_h[row * Hn + (c - Wn)];
        }
        sIt[rr][c] = v;
    }
    __syncthreads();
    int f = tid & 63, r0 = tid >> 6;
#pragma unroll
    for (int q = 0; q < 4; q++) {
        int rr = r0 + q * 4;
        float acc = 0.f;
#pragma unroll
        for (int c = 0; c < FGn; c++) acc += sIt[rr][c] * sW[c * EDn + f];
        g_XW[(row0 + rr) * EDn + f] = acc;
    }
}

// -------- per-step kernel 2: df = AnT @ XW + b ; de1/de2 = tanh(df@W +b) --------
__global__ __launch_bounds__(256) void k_df_de(const float* __restrict__ gconv_b,
                                               const float* __restrict__ w1, const float* __restrict__ b1,
                                               const float* __restrict__ w2, const float* __restrict__ b2) {
    __shared__ float aT[32][33];
    __shared__ float xwS[32][64];
    __shared__ float dfS[32][64];
    __shared__ float wS[64 * 64];
    int b = blockIdx.y, jT = blockIdx.x;
    int tid = threadIdx.x;
    int f = tid & 63, jg = tid >> 6;  // jg in 0..3
    int j0 = jT * 32;
    float acc[8];
#pragma unroll
    for (int q = 0; q < 8; q++) acc[q] = 0.f;

    for (int ic = 0; ic < Nn; ic += 32) {
        for (int i = tid; i < 32 * 32; i += 256) {
            int jj = i >> 5, ii = i & 31;
            aT[jj][ii] = g_AnT[(j0 + jj) * Nn + ic + ii];
        }
        for (int i = tid; i < 32 * 64; i += 256) {
            int ii = i >> 6, ff = i & 63;
            xwS[ii][ff] = g_XW[(b * Nn + ic + ii) * EDn + ff];
        }
        __syncthreads();
#pragma unroll 4
        for (int ii = 0; ii < 32; ii++) {
            float xv = xwS[ii][f];
#pragma unroll
            for (int q = 0; q < 8; q++) acc[q] += aT[jg + q * 4][ii] * xv;
        }
        __syncthreads();
    }
    float gb = gconv_b[f];
#pragma unroll
    for (int q = 0; q < 8; q++) dfS[jg + q * 4][f] = acc[q] + gb;
    __syncthreads();

    // de1
    for (int i = tid; i < 4096; i += 256) wS[i] = w1[i];
    __syncthreads();
    {
        float bb = b1[f];
#pragma unroll
        for (int q = 0; q < 8; q++) {
            int jj = jg + q * 4;
            float a = bb;
#pragma unroll
            for (int ff = 0; ff < 64; ff++) a += dfS[jj][ff] * wS[ff * 64 + f];
            g_de1[(b * Nn + j0 + jj) * EDn + f] = tanhf(a);
        }
    }
    __syncthreads();
    // de2
    for (int i = tid; i < 4096; i += 256) wS[i] = w2[i];
    __syncthreads();
    {
        float bb = b2[f];
#pragma unroll
        for (int q = 0; q < 8; q++) {
            int jj = jg + q * 4;
            float a = bb;
#pragma unroll
            for (int ff = 0; ff < 64; ff++) a += dfS[jj][ff] * wS[ff * 64 + f];
            g_de2[(b * Nn + j0 + jj) * EDn + f] = tanhf(a);
        }
    }
}

// -------- per-step kernel 3: Et tiles + ring buffer + running sum + colsums --------
__global__ __launch_bounds__(256) void k_et(int slot) {
    __shared__ float d1i[32][65], d2i[32][65], d1j[32][65], d2j[32][65];
    __shared__ float tS[32][33];
    __shared__ float colbuf[64];
    int b = blockIdx.y;
    int tid = threadIdx.x;
    // decode triangular pair index -> (iT, jT), iT <= jT, 8 tiles per dim
    int p = blockIdx.x, iT = 0;
    while (p >= 8 - iT) { p -= 8 - iT; iT++; }
    int jT = iT + p;
    bool diag = (iT == jT);

    for (int i = tid; i < 32 * 64; i += 256) {
        int rr = i >> 6, e = i & 63;
        int gi = iT * 32 + rr, gj = jT * 32 + rr;
        d1i[rr][e] = g_de1[(b * Nn + gi) * EDn + e];
        d2i[rr][e] = g_de2[(b * Nn + gi) * EDn + e];
        d1j[rr][e] = g_de1[(b * Nn + gj) * EDn + e];
        d2j[rr][e] = g_de2[(b * Nn + gj) * EDn + e];
    }
    if (tid < 64) colbuf[tid] = 0.f;
    __syncthreads();

#pragma unroll
    for (int q = 0; q < 4; q++) {
        int idx = tid + q * 256;
        int ii = idx >> 5, jj = idx & 31;
        float a = 0.f, bb = 0.f;
#pragma unroll
        for (int e = 0; e < 64; e++) {
            a += d1i[ii][e] * d2j[jj][e];
            bb += d1j[jj][e] * d2i[ii][e];
        }
        tS[ii][jj] = tanhf(a - bb);
    }
    __syncthreads();

    // tile (iT, jT)
#pragma unroll
    for (int q = 0; q < 4; q++) {
        int idx = tid + q * 256;
        int ii = idx >> 5, jj = idx & 31;
        float et = fmaxf(tS[ii][jj], 0.f);
        int gi = iT * 32 + ii, gj = jT * 32 + jj;
        size_t eoff = (((size_t)(b * Sn + slot) * Nn + gi)) * Nn + gj;
        float old = g_Eh[eoff];
        g_Eh[eoff] = et;
        float delta = et - old;
        size_t moff = ((size_t)b * Nn + gi) * Nn + gj;
        g_Msum[moff] += delta;
        atomicAdd(&colbuf[jj], delta);
    }
    if (!diag) {
        // tile (jT, iT): row a in j-range, col c in i-range, value = relu(-t[c][a])
#pragma unroll
        for (int q = 0; q < 4; q++) {
            int idx = tid + q * 256;
            int a = idx >> 5, c = idx & 31;
            float et = fmaxf(-tS[c][a], 0.f);
            int gi = jT * 32 + a, gj = iT * 32 + c;
            size_t eoff = (((size_t)(b * Sn + slot) * Nn + gi)) * Nn + gj;
            float old = g_Eh[eoff];
            g_Eh[eoff] = et;
            float delta = et - old;
            size_t moff = ((size_t)b * Nn + gi) * Nn + gj;
            g_Msum[moff] += delta;
            atomicAdd(&colbuf[32 + c], delta);
        }
    }
    __syncthreads();
    if (tid < 32) atomicAdd(&g_colsum[b * Nn + jT * 32 + tid], colbuf[tid]);
    if (!diag && tid >= 32 && tid < 64)
        atomicAdd(&g_colsum[b * Nn + iT * 32 + (tid - 32)], colbuf[tid]);
}

// -------- per-step kernel 4: s-reduction + fused GRU update --------
__global__ __launch_bounds__(256) void k_gru(const float* __restrict__ x,
                                             const float* __restrict__ wz_l, const float* __restrict__ bz_l,
                                             const float* __restrict__ wr_l, const float* __restrict__ br_l,
                                             const float* __restrict__ wh_l, const float* __restrict__ bh_l,
                                             int t, float cnt) {
    __shared__ float dinvS[256];
    __shared__ float dxv[256];
    __shared__ float part[8][32];
    __shared__ float sS[32];
    __shared__ float hS[32][64];
    __shared__ float zS[32][64];
    __shared__ float hrS[32][64];
    __shared__ float wS[64 * 64];
    __shared__ float coefS[6 * 64];

    int b = blockIdx.y;
    int n0 = blockIdx.x * 32;
    int tid = threadIdx.x;
    float inv_cnt = 1.0f / cnt;

    {   // dinv and dinv*x for all 256 nodes of this batch
        int i = tid;
        float cs = g_colsum[b * Nn + i];
        float dv = 1.0f / sqrtf(cs * inv_cnt + 1.0f);
        dinvS[i] = dv;
        dxv[i] = dv * x[(b * Nn + i) * Tn + t];
    }
    __syncthreads();

    {   // partial column reductions of Msum over i for the 32 owned columns
        int c = tid & 31, g = tid >> 5;  // 8 groups of 32 i's
        float acc = 0.f;
        int ibase = g * 32;
#pragma unroll 8
        for (int k = 0; k < 32; k++) {
            int i = ibase + k;
            acc += g_Msum[((size_t)b * Nn + i) * Nn + n0 + c] * dxv[i];
        }
        part[g][c] = acc;
    }
    __syncthreads();
    if (tid < 32) {
        float sraw = 0.f;
#pragma unroll
        for (int g = 0; g < 8; g++) sraw += part[g][tid];
        int n = n0 + tid;
        float dj = dinvS[n];
        sS[tid] = dj * (sraw * inv_cnt + dj * x[(b * Nn + n) * Tn + t]);
    }
    for (int i = tid; i < 32 * 64; i += 256) {
        int rr = i >> 6, ff = i & 63;
        hS[rr][ff] = g_h[(b * Nn + n0 + rr) * Hn + ff];
    }
    for (int i = tid; i < 384; i += 256) coefS[i] = g_coef[i];
    __syncthreads();

    int k = tid & 63, rg = tid >> 6;  // 4 row groups; rows rg, rg+4, ..., rg+28

    // z = sigmoid(s*az + cz0 + h @ Wz2 + bz)
    for (int i = tid; i < 4096; i += 256) wS[i] = wz_l[(Hn + (i >> 6)) * Hn + (i & 63)];
    __syncthreads();
    {
        float bz = bz_l[k];
#pragma unroll
        for (int q = 0; q < 8; q++) {
            int rr = rg + q * 4;
            float a = sS[rr] * coefS[k] + coefS[64 + k] + bz;
#pragma unroll
            for (int ff = 0; ff < 64; ff++) a += hS[rr][ff] * wS[ff * 64 + k];
            zS[rr][k] = 1.0f / (1.0f + expf(-a));
        }
    }
    __syncthreads();
    // r -> hr = h * r
    for (int i = tid; i < 4096; i += 256) wS[i] = wr_l[(Hn + (i >> 6)) * Hn + (i & 63)];
    __syncthreads();
    {
        float br = br_l[k];
#pragma unroll
        for (int q = 0; q < 8; q++) {
            int rr = rg + q * 4;
            float a = sS[rr] * coefS[128 + k] + coefS[192 + k] + br;
#pragma unroll
            for (int ff = 0; ff < 64; ff++) a += hS[rr][ff] * wS[ff * 64 + k];
            float r = 1.0f / (1.0f + expf(-a));
            hrS[rr][k] = hS[rr][k] * r;
        }
    }
    __syncthreads();
    // ht = tanh(s*ah + ch0 + hr @ Wh2 + bh); h = z*h + (1-z)*ht
    for (int i = tid; i < 4096; i += 256) wS[i] = wh_l[(Hn + (i >> 6)) * Hn + (i & 63)];
    __syncthreads();
    {
        float bh = bh_l[k];
#pragma unroll
        for (int q = 0; q < 8; q++) {
            int rr = rg + q * 4;
            float a = sS[rr] * coefS[256 + k] + coefS[320 + k] + bh;
#pragma unroll
            for (int ff = 0; ff < 64; ff++) a += hrS[rr][ff] * wS[ff * 64 + k];
            float ht = tanhf(a);
            float z = zS[rr][k];
            g_h[(b * Nn + n0 + rr) * Hn + k] = z * hS[rr][k] + (1.0f - z) * ht;
        }
    }
}

// ---------------- final classifier ----------------
__global__ __launch_bounds__(256) void k_cls(const float* __restrict__ cls_w,
                                             const float* __restrict__ cls_b,
                                             float* __restrict__ out) {
    int b = blockIdx.x, tid = threadIdx.x;
    float acc[4] = {0.f, 0.f, 0.f, 0.f};
    for (int i = tid; i < Nn * Hn; i += 256) {
        float hv = g_h[b * Nn * Hn + i];
#pragma unroll
        for (int c = 0; c < 4; c++) acc[c] += hv * cls_w[i * Cn + c];
    }
    __shared__ float red[4][256];
#pragma unroll
    for (int c = 0; c < 4; c++) red[c][tid] = acc[c];
    __syncthreads();
    for (int s = 128; s > 0; s >>= 1) {
        if (tid < s) {
#pragma unroll
            for (int c = 0; c < 4; c++) red[c][tid] += red[c][tid + s];
        }
        __syncthreads();
    }
    if (tid < 4) out[b * Cn + tid] = red[tid][0] + cls_b[tid];
}

// ---------------- launch ----------------
extern "C" void kernel_launch(void* const* d_in, const int* in_sizes, int n_in,
                              void* d_out, int out_size) {
    const float* x        = (const float*)d_in[0];
    const float* ew       = (const float*)d_in[1];
    const float* gconv_w  = (const float*)d_in[2];
    const float* gconv_b  = (const float*)d_in[3];
    const float* w1       = (const float*)d_in[4];
    const float* b1       = (const float*)d_in[5];
    const float* w2       = (const float*)d_in[6];
    const float* b2       = (const float*)d_in[7];
    const float* wz_c     = (const float*)d_in[8];
    const float* bz_c     = (const float*)d_in[9];
    const float* wz_l     = (const float*)d_in[10];
    const float* bz_l     = (const float*)d_in[11];
    const float* wr_c     = (const float*)d_in[12];
    const float* br_c     = (const float*)d_in[13];
    const float* wr_l     = (const float*)d_in[14];
    const float* br_l     = (const float*)d_in[15];
    const float* wh_c     = (const float*)d_in[16];
    const float* bh_c     = (const float*)d_in[17];
    const float* wh_l     = (const float*)d_in[18];
    const float* bh_l     = (const float*)d_in[19];
    const float* cls_w    = (const float*)d_in[20];
    const float* cls_b    = (const float*)d_in[21];
    const int*   eidx     = (const int*)d_in[22];
    float* out = (float*)d_out;

    k_zero<<<2048, 256>>>();
    k_scatter<<<(En + 255) / 256, 256>>>(eidx, ew);
    k_statdeg<<<1, 256>>>();
    k_statAnT<<<(Nn * Nn + 255) / 256, 256>>>();
    k_precoef<<<1, 64>>>(wz_c, wz_l, bz_c, wr_c, wr_l, br_c, wh_c, wh_l, bh_c);

    for (int t = 0; t < Tn; t++) {
        int slot = t % Sn;
        float cnt = (float)((t + 1 < Sn) ? (t + 1) : Sn);
        k_xw<<<Bn * Nn / 16, 256>>>(x, gconv_w, t);
        k_df_de<<<dim3(8, Bn), 256>>>(gconv_b, w1, b1, w2, b2);
        k_et<<<dim3(36, Bn), 256>>>(slot);
        k_gru<<<dim3(8, Bn), 256>>>(x, wz_l, bz_l, wr_l, br_l, wh_l, bh_l, t, cnt);
    }

    k_cls<<<Bn, 256>>>(cls_w, cls_b, out);
}

// round 6
// speedup vs baseline: 1.0006x; 1.0006x over previous
#include <cuda_runtime.h>
#include <math.h>

#define Bn 16
#define Nn 256
#define Tn 64
#define Wn 12
#define Hn 64
#define EDn 64
#define Sn 5
#define Cn 4
#define En 2048
#define FGn 76   // W + H

// ---------------- device scratch (no allocation allowed) ----------------
__device__ float g_A[Nn * Nn];                 // static adjacency accumulator
__device__ float g_AnT[Nn * Nn];               // normalized static adj, transposed [j][i]
__device__ float g_dinv_stat[Nn];
__device__ float g_coef[6 * Hn];               // az, cz0, ar, cr0, ah, ch0
__device__ float g_XW[Bn * Nn * EDn];
__device__ float g_de1[Bn * Nn * EDn];
__device__ float g_de2[Bn * Nn * EDn];
__device__ float g_Eh[(size_t)Bn * Sn * Nn * Nn];   // ring buffer of Et
__device__ float g_Msum[(size_t)Bn * Nn * Nn];      // running sum over ring slots
__device__ float g_colsum[Bn * Nn];                 // column sums of Msum
__device__ float g_h[Bn * Nn * Hn];

// ---------------- setup kernels ----------------
__global__ void k_zero() {
    size_t idx = (size_t)blockIdx.x * blockDim.x + threadIdx.x;
    size_t str = (size_t)gridDim.x * blockDim.x;
    for (size_t i = idx; i < (size_t)Nn * Nn; i += str) g_A[i] = 0.f;
    for (size_t i = idx; i < (size_t)Bn * Sn * Nn * Nn; i += str) g_Eh[i] = 0.f;
    for (size_t i = idx; i < (size_t)Bn * Nn * Nn; i += str) g_Msum[i] = 0.f;
    for (size_t i = idx; i < (size_t)Bn * Nn; i += str) g_colsum[i] = 0.f;
    for (size_t i = idx; i < (size_t)Bn * Nn * Hn; i += str) g_h[i] = 0.f;
}

__global__ void k_scatter(const int* __restrict__ ei, const float* __restrict__ ew) {
    int e = blockIdx.x * blockDim.x + threadIdx.x;
    if (e < En) atomicAdd(&g_A[ei[e] * Nn + ei[En + e]], ew[e]);
}

__global__ void k_statdeg() {
    int j = threadIdx.x;  // 256 threads, 1 block
    float d = 1.0f;       // self loop
    for (int i = 0; i < Nn; i++) d += g_A[i * Nn + j];
    g_dinv_stat[j] = 1.0f / sqrtf(d);
}

__global__ void k_statAnT() {
    int idx = blockIdx.x * blockDim.x + threadIdx.x;
    if (idx >= Nn * Nn) return;
    int j = idx / Nn, i = idx % Nn;
    float a = g_A[i * Nn + j] + (i == j ? 1.0f : 0.0f);
    g_AnT[idx] = g_dinv_stat[i] * a * g_dinv_stat[j];
}

__global__ void k_precoef(const float* wz_c, const float* wz_l, const float* bz_c,
                          const float* wr_c, const float* wr_l, const float* br_c,
                          const float* wh_c, const float* wh_l, const float* bh_c) {
    int k = threadIdx.x;  // 64 threads
    float az = 0, cz = 0, ar = 0, cr = 0, ah = 0, ch = 0;
    for (int f = 0; f < Hn; f++) {
        float wzl = wz_l[f * Hn + k], wrl = wr_l[f * Hn + k], whl = wh_l[f * Hn + k];
        az += wz_c[f] * wzl;  cz += bz_c[f] * wzl;
        ar += wr_c[f] * wrl;  cr += br_c[f] * wrl;
        ah += wh_c[f] * whl;  ch += bh_c[f] * whl;
    }
    g_coef[k] = az;        g_coef[64 + k] = cz;
    g_coef[128 + k] = ar;  g_coef[192 + k] = cr;
    g_coef[256 + k] = ah;  g_coef[320 + k] = ch;
}

// ---------------- per-step kernel 1: XW = concat(win, h) @ Wg ----------------
__global__ __launch_bounds__(256) void k_xw(const float* __restrict__ x,
                                            const float* __restrict__ Wg, int t) {
    __shared__ float sW[FGn * EDn];     // 76*64
    __shared__ float sIt[16][FGn];
    int tid = threadIdx.x;
    for (int i = tid; i < FGn * EDn; i += 256) sW[i] = Wg[i];
    int row0 = blockIdx.x * 16;
    for (int i = tid; i < 16 * FGn; i += 256) {
        int rr = i / FGn, c = i % FGn;
        int row = row0 + rr;
        float v;
        if (c < Wn) {
            int tt = t + c - (Wn - 1);
            v = (tt >= 0) ? x[row * Tn + tt] : 0.0f;
        } else {
            v = g_h[row * Hn + (c - Wn)];
        }
        sIt[rr][c] = v;
    }
    __syncthreads();
    int f = tid & 63, r0 = tid >> 6;
#pragma unroll
    for (int q = 0; q < 4; q++) {
        int rr = r0 + q * 4;
        float acc = 0.f;
#pragma unroll
        for (int c = 0; c < FGn; c++) acc += sIt[rr][c] * sW[c * EDn + f];
        g_XW[(row0 + rr) * EDn + f] = acc;
    }
}

// -------- per-step kernel 2: df = AnT @ XW + b ; de1/de2 = tanh(df@W +b) --------
__global__ __launch_bounds__(256) void k_df_de(const float* __restrict__ gconv_b,
                                               const float* __restrict__ w1, const float* __restrict__ b1,
                                               const float* __restrict__ w2, const float* __restrict__ b2) {
    __shared__ float aT[32][33];
    __shared__ float xwS[32][64];
    __shared__ float dfS[32][64];
    __shared__ float wS[64 * 64];
    int b = blockIdx.y, jT = blockIdx.x;
    int tid = threadIdx.x;
    int f = tid & 63, jg = tid >> 6;  // jg in 0..3
    int j0 = jT * 32;
    float acc[8];
#pragma unroll
    for (int q = 0; q < 8; q++) acc[q] = 0.f;

    for (int ic = 0; ic < Nn; ic += 32) {
        for (int i = tid; i < 32 * 32; i += 256) {
            int jj = i >> 5, ii = i & 31;
            aT[jj][ii] = g_AnT[(j0 + jj) * Nn + ic + ii];
        }
        for (int i = tid; i < 32 * 64; i += 256) {
            int ii = i >> 6, ff = i & 63;
            xwS[ii][ff] = g_XW[(b * Nn + ic + ii) * EDn + ff];
        }
        __syncthreads();
#pragma unroll 4
        for (int ii = 0; ii < 32; ii++) {
            float xv = xwS[ii][f];
#pragma unroll
            for (int q = 0; q < 8; q++) acc[q] += aT[jg + q * 4][ii] * xv;
        }
        __syncthreads();
    }
    float gb = gconv_b[f];
#pragma unroll
    for (int q = 0; q < 8; q++) dfS[jg + q * 4][f] = acc[q] + gb;
    __syncthreads();

    // de1
    for (int i = tid; i < 4096; i += 256) wS[i] = w1[i];
    __syncthreads();
    {
        float bb = b1[f];
#pragma unroll
        for (int q = 0; q < 8; q++) {
            int jj = jg + q * 4;
            float a = bb;
#pragma unroll
            for (int ff = 0; ff < 64; ff++) a += dfS[jj][ff] * wS[ff * 64 + f];
            g_de1[(b * Nn + j0 + jj) * EDn + f] = tanhf(a);
        }
    }
    __syncthreads();
    // de2
    for (int i = tid; i < 4096; i += 256) wS[i] = w2[i];
    __syncthreads();
    {
        float bb = b2[f];
#pragma unroll
        for (int q = 0; q < 8; q++) {
            int jj = jg + q * 4;
            float a = bb;
#pragma unroll
            for (int ff = 0; ff < 64; ff++) a += dfS[jj][ff] * wS[ff * 64 + f];
            g_de2[(b * Nn + j0 + jj) * EDn + f] = tanhf(a);
        }
    }
}

// -------- per-step kernel 3: Et tiles + ring buffer + running sum + colsums --------
__global__ __launch_bounds__(256) void k_et(int slot) {
    __shared__ float d1i[32][65], d2i[32][65], d1j[32][65], d2j[32][65];
    __shared__ float tS[32][33];
    __shared__ float colbuf[64];
    int b = blockIdx.y;
    int tid = threadIdx.x;
    // decode triangular pair index -> (iT, jT), iT <= jT, 8 tiles per dim
    int p = blockIdx.x, iT = 0;
    while (p >= 8 - iT) { p -= 8 - iT; iT++; }
    int jT = iT + p;
    bool diag = (iT == jT);

    for (int i = tid; i < 32 * 64; i += 256) {
        int rr = i >> 6, e = i & 63;
        int gi = iT * 32 + rr, gj = jT * 32 + rr;
        d1i[rr][e] = g_de1[(b * Nn + gi) * EDn + e];
        d2i[rr][e] = g_de2[(b * Nn + gi) * EDn + e];
        d1j[rr][e] = g_de1[(b * Nn + gj) * EDn + e];
        d2j[rr][e] = g_de2[(b * Nn + gj) * EDn + e];
    }
    if (tid < 64) colbuf[tid] = 0.f;
    __syncthreads();

#pragma unroll
    for (int q = 0; q < 4; q++) {
        int idx = tid + q * 256;
        int ii = idx >> 5, jj = idx & 31;
        float a = 0.f, bb = 0.f;
#pragma unroll
        for (int e = 0; e < 64; e++) {
            a += d1i[ii][e] * d2j[jj][e];
            bb += d1j[jj][e] * d2i[ii][e];
        }
        tS[ii][jj] = tanhf(a - bb);
    }
    __syncthreads();

    // tile (iT, jT)
#pragma unroll
    for (int q = 0; q < 4; q++) {
        int idx = tid + q * 256;
        int ii = idx >> 5, jj = idx & 31;
        float et = fmaxf(tS[ii][jj], 0.f);
        int gi = iT * 32 + ii, gj = jT * 32 + jj;
        size_t eoff = (((size_t)(b * Sn + slot) * Nn + gi)) * Nn + gj;
        float old = g_Eh[eoff];
        g_Eh[eoff] = et;
        float delta = et - old;
        size_t moff = ((size_t)b * Nn + gi) * Nn + gj;
        g_Msum[moff] += delta;
        atomicAdd(&colbuf[jj], delta);
    }
    if (!diag) {
        // tile (jT, iT): row a in j-range, col c in i-range, value = relu(-t[c][a])
#pragma unroll
        for (int q = 0; q < 4; q++) {
            int idx = tid + q * 256;
            int a = idx >> 5, c = idx & 31;
            float et = fmaxf(-tS[c][a], 0.f);
            int gi = jT * 32 + a, gj = iT * 32 + c;
            size_t eoff = (((size_t)(b * Sn + slot) * Nn + gi)) * Nn + gj;
            float old = g_Eh[eoff];
            g_Eh[eoff] = et;
            float delta = et - old;
            size_t moff = ((size_t)b * Nn + gi) * Nn + gj;
            g_Msum[moff] += delta;
            atomicAdd(&colbuf[32 + c], delta);
        }
    }
    __syncthreads();
    if (tid < 32) atomicAdd(&g_colsum[b * Nn + jT * 32 + tid], colbuf[tid]);
    if (!diag && tid >= 32 && tid < 64)
        atomicAdd(&g_colsum[b * Nn + iT * 32 + (tid - 32)], colbuf[tid]);
}

// -------- per-step kernel 4: s-reduction + fused GRU update --------
__global__ __launch_bounds__(256) void k_gru(const float* __restrict__ x,
                                             const float* __restrict__ wz_l, const float* __restrict__ bz_l,
                                             const float* __restrict__ wr_l, const float* __restrict__ br_l,
                                             const float* __restrict__ wh_l, const float* __restrict__ bh_l,
                                             int t, float cnt) {
    __shared__ float dinvS[256];
    __shared__ float dxv[256];
    __shared__ float part[8][32];
    __shared__ float sS[32];
    __shared__ float hS[32][64];
    __shared__ float zS[32][64];
    __shared__ float hrS[32][64];
    __shared__ float wS[64 * 64];
    __shared__ float coefS[6 * 64];

    int b = blockIdx.y;
    int n0 = blockIdx.x * 32;
    int tid = threadIdx.x;
    float inv_cnt = 1.0f / cnt;

    {   // dinv and dinv*x for all 256 nodes of this batch
        int i = tid;
        float cs = g_colsum[b * Nn + i];
        float dv = 1.0f / sqrtf(cs * inv_cnt + 1.0f);
        dinvS[i] = dv;
        dxv[i] = dv * x[(b * Nn + i) * Tn + t];
    }
    __syncthreads();

    {   // partial column reductions of Msum over i for the 32 owned columns
        int c = tid & 31, g = tid >> 5;  // 8 groups of 32 i's
        float acc = 0.f;
        int ibase = g * 32;
#pragma unroll 8
        for (int k = 0; k < 32; k++) {
            int i = ibase + k;
            acc += g_Msum[((size_t)b * Nn + i) * Nn + n0 + c] * dxv[i];
        }
        part[g][c] = acc;
    }
    __syncthreads();
    if (tid < 32) {
        float sraw = 0.f;
#pragma unroll
        for (int g = 0; g < 8; g++) sraw += part[g][tid];
        int n = n0 + tid;
        float dj = dinvS[n];
        sS[tid] = dj * (sraw * inv_cnt + dj * x[(b * Nn + n) * Tn + t]);
    }
    for (int i = tid; i < 32 * 64; i += 256) {
        int rr = i >> 6, ff = i & 63;
        hS[rr][ff] = g_h[(b * Nn + n0 + rr) * Hn + ff];
    }
    for (int i = tid; i < 384; i += 256) coefS[i] = g_coef[i];
    __syncthreads();

    int k = tid & 63, rg = tid >> 6;  // 4 row groups; rows rg, rg+4, ..., rg+28

    // z = sigmoid(s*az + cz0 + h @ Wz2 + bz)
    for (int i = tid; i < 4096; i += 256) wS[i] = wz_l[(Hn + (i >> 6)) * Hn + (i & 63)];
    __syncthreads();
    {
        float bz = bz_l[k];
#pragma unroll
        for (int q = 0; q < 8; q++) {
            int rr = rg + q * 4;
            float a = sS[rr] * coefS[k] + coefS[64 + k] + bz;
#pragma unroll
            for (int ff = 0; ff < 64; ff++) a += hS[rr][ff] * wS[ff * 64 + k];
            zS[rr][k] = 1.0f / (1.0f + expf(-a));
        }
    }
    __syncthreads();
    // r -> hr = h * r
    for (int i = tid; i < 4096; i += 256) wS[i] = wr_l[(Hn + (i >> 6)) * Hn + (i & 63)];
    __syncthreads();
    {
        float br = br_l[k];
#pragma unroll
        for (int q = 0; q < 8; q++) {
            int rr = rg + q * 4;
            float a = sS[rr] * coefS[128 + k] + coefS[192 + k] + br;
#pragma unroll
            for (int ff = 0; ff < 64; ff++) a += hS[rr][ff] * wS[ff * 64 + k];
            float r = 1.0f / (1.0f + expf(-a));
            hrS[rr][k] = hS[rr][k] * r;
        }
    }
    __syncthreads();
    // ht = tanh(s*ah + ch0 + hr @ Wh2 + bh); h = z*h + (1-z)*ht
    for (int i = tid; i < 4096; i += 256) wS[i] = wh_l[(Hn + (i >> 6)) * Hn + (i & 63)];
    __syncthreads();
    {
        float bh = bh_l[k];
#pragma unroll
        for (int q = 0; q < 8; q++) {
            int rr = rg + q * 4;
            float a = sS[rr] * coefS[256 + k] + coefS[320 + k] + bh;
#pragma unroll
            for (int ff = 0; ff < 64; ff++) a += hrS[rr][ff] * wS[ff * 64 + k];
            float ht = tanhf(a);
            float z = zS[rr][k];
            g_h[(b * Nn + n0 + rr) * Hn + k] = z * hS[rr][k] + (1.0f - z) * ht;
        }
    }
}

// ---------------- final classifier ----------------
__global__ __launch_bounds__(256) void k_cls(const float* __restrict__ cls_w,
                                             const float* __restrict__ cls_b,
                                             float* __restrict__ out) {
    int b = blockIdx.x, tid = threadIdx.x;
    float acc[4] = {0.f, 0.f, 0.f, 0.f};
    for (int i = tid; i < Nn * Hn; i += 256) {
        float hv = g_h[b * Nn * Hn + i];
#pragma unroll
        for (int c = 0; c < 4; c++) acc[c] += hv * cls_w[i * Cn + c];
    }
    __shared__ float red[4][256];
#pragma unroll
    for (int c = 0; c < 4; c++) red[c][tid] = acc[c];
    __syncthreads();
    for (int s = 128; s > 0; s >>= 1) {
        if (tid < s) {
#pragma unroll
            for (int c = 0; c < 4; c++) red[c][tid] += red[c][tid + s];
        }
        __syncthreads();
    }
    if (tid < 4) out[b * Cn + tid] = red[tid][0] + cls_b[tid];
}

// ---------------- launch ----------------
extern "C" void kernel_launch(void* const* d_in, const int* in_sizes, int n_in,
                              void* d_out, int out_size) {
    const float* x        = (const float*)d_in[0];
    const float* ew       = (const float*)d_in[1];
    const float* gconv_w  = (const float*)d_in[2];
    const float* gconv_b  = (const float*)d_in[3];
    const float* w1       = (const float*)d_in[4];
    const float* b1       = (const float*)d_in[5];
    const float* w2       = (const float*)d_in[6];
    const float* b2       = (const float*)d_in[7];
    const float* wz_c     = (const float*)d_in[8];
    const float* bz_c     = (const float*)d_in[9];
    const float* wz_l     = (const float*)d_in[10];
    const float* bz_l     = (const float*)d_in[11];
    const float* wr_c     = (const float*)d_in[12];
    const float* br_c     = (const float*)d_in[13];
    const float* wr_l     = (const float*)d_in[14];
    const float* br_l     = (const float*)d_in[15];
    const float* wh_c     = (const float*)d_in[16];
    const float* bh_c     = (const float*)d_in[17];
    const float* wh_l     = (const float*)d_in[18];
    const float* bh_l     = (const float*)d_in[19];
    const float* cls_w    = (const float*)d_in[20];
    const float* cls_b    = (const float*)d_in[21];
    const int*   eidx     = (const int*)d_in[22];
    float* out = (float*)d_out;

    k_zero<<<2048, 256>>>();
    k_scatter<<<(En + 255) / 256, 256>>>(eidx, ew);
    k_statdeg<<<1, 256>>>();
    k_statAnT<<<(Nn * Nn + 255) / 256, 256>>>();
    k_precoef<<<1, 64>>>(wz_c, wz_l, bz_c, wr_c, wr_l, br_c, wh_c, wh_l, bh_c);

    for (int t = 0; t < Tn; t++) {
        int slot = t % Sn;
        float cnt = (float)((t + 1 < Sn) ? (t + 1) : Sn);
        k_xw<<<Bn * Nn / 16, 256>>>(x, gconv_w, t);
        k_df_de<<<dim3(8, Bn), 256>>>(gconv_b, w1, b1, w2, b2);
        k_et<<<dim3(36, Bn), 256>>>(slot);
        k_gru<<<dim3(8, Bn), 256>>>(x, wz_l, bz_l, wr_l, br_l, wh_l, bh_l, t, cnt);
    }

    k_cls<<<Bn, 256>>>(cls_w, cls_b, out);
}

// round 7
// speedup vs baseline: 1.4824x; 1.4815x over previous
#include <cuda_runtime.h>
#include <math.h>

#define Bn 16
#define Nn 256
#define Tn 64
#define Wn 12
#define Hn 64
#define EDn 64
#define Sn 5
#define Cn 4
#define En 2048
#define FGn 76   // W + H

// ---------------- device scratch (no allocation allowed) ----------------
__device__ float g_A[Nn * Nn];
__device__ float g_AnT[Nn * Nn];               // normalized static adj, transposed [j][i]
__device__ float g_dinv_stat[Nn];
__device__ float g_coef[6 * Hn];               // az, cz0, ar, cr0, ah, ch0
__device__ float g_XW[Bn * Nn * EDn];
__device__ float g_de1[Bn * Nn * EDn];
__device__ float g_de2[Bn * Nn * EDn];
__device__ float g_Eh[(size_t)Bn * Sn * Nn * Nn];   // ring buffer of Et
__device__ float g_Msum[(size_t)Bn * Nn * Nn];      // running sum over ring slots
__device__ float g_colsum[Bn * Nn];                 // column sums of Msum
__device__ float g_h[Bn * Nn * Hn];

// ---------------- setup kernels ----------------
__global__ void k_zero() {
    size_t idx = (size_t)blockIdx.x * blockDim.x + threadIdx.x;
    size_t str = (size_t)gridDim.x * blockDim.x;
    for (size_t i = idx; i < (size_t)Nn * Nn; i += str) g_A[i] = 0.f;
    for (size_t i = idx; i < (size_t)Bn * Sn * Nn * Nn; i += str) g_Eh[i] = 0.f;
    for (size_t i = idx; i < (size_t)Bn * Nn * Nn; i += str) g_Msum[i] = 0.f;
    for (size_t i = idx; i < (size_t)Bn * Nn; i += str) g_colsum[i] = 0.f;
    for (size_t i = idx; i < (size_t)Bn * Nn * Hn; i += str) g_h[i] = 0.f;
}

__global__ void k_scatter(const int* __restrict__ ei, const float* __restrict__ ew) {
    int e = blockIdx.x * blockDim.x + threadIdx.x;
    if (e < En) atomicAdd(&g_A[ei[e] * Nn + ei[En + e]], ew[e]);
}

__global__ void k_statdeg() {
    int j = threadIdx.x;
    float d = 1.0f;
    for (int i = 0; i < Nn; i++) d += g_A[i * Nn + j];
    g_dinv_stat[j] = 1.0f / sqrtf(d);
}

__global__ void k_statAnT() {
    int idx = blockIdx.x * blockDim.x + threadIdx.x;
    if (idx >= Nn * Nn) return;
    int j = idx / Nn, i = idx % Nn;
    float a = g_A[i * Nn + j] + (i == j ? 1.0f : 0.0f);
    g_AnT[idx] = g_dinv_stat[i] * a * g_dinv_stat[j];
}

__global__ void k_precoef(const float* wz_c, const float* wz_l, const float* bz_c,
                          const float* wr_c, const float* wr_l, const float* br_c,
                          const float* wh_c, const float* wh_l, const float* bh_c) {
    int k = threadIdx.x;  // 64 threads
    float az = 0, cz = 0, ar = 0, cr = 0, ah = 0, ch = 0;
    for (int f = 0; f < Hn; f++) {
        float wzl = wz_l[f * Hn + k], wrl = wr_l[f * Hn + k], whl = wh_l[f * Hn + k];
        az += wz_c[f] * wzl;  cz += bz_c[f] * wzl;
        ar += wr_c[f] * wrl;  cr += br_c[f] * wrl;
        ah += wh_c[f] * whl;  ch += bh_c[f] * whl;
    }
    g_coef[k] = az;        g_coef[64 + k] = cz;
    g_coef[128 + k] = ar;  g_coef[192 + k] = cr;
    g_coef[256 + k] = ah;  g_coef[320 + k] = ch;
}

// ---------------- per-step kernel 1: XW = concat(win, h) @ Wg ----------------
__global__ __launch_bounds__(256) void k_xw(const float* __restrict__ x,
                                            const float* __restrict__ Wg, int t) {
    __shared__ float sW[FGn * EDn];       // [c][f]
    __shared__ float sIt[32][80];         // padded for float4
    int tid = threadIdx.x;
    for (int i = tid; i < FGn * EDn; i += 256) sW[i] = Wg[i];
    int row0 = blockIdx.x * 32;
    for (int i = tid; i < 32 * FGn; i += 256) {
        int rr = i / FGn, c = i - rr * FGn;
        int row = row0 + rr;
        float v;
        if (c < Wn) {
            int tt = t + c - (Wn - 1);
            v = (tt >= 0) ? x[row * Tn + tt] : 0.0f;
        } else {
            v = g_h[row * Hn + (c - Wn)];
        }
        sIt[rr][c] = v;
    }
    __syncthreads();

    int tx = tid & 31, ty = tid >> 5;
    int f0 = tx * 2, r0 = ty * 4;
    float acc[4][2];
#pragma unroll
    for (int jy = 0; jy < 4; jy++) { acc[jy][0] = 0.f; acc[jy][1] = 0.f; }

#pragma unroll 4
    for (int c = 0; c < FGn; c += 4) {
        float4 A[4];
#pragma unroll
        for (int jy = 0; jy < 4; jy++) A[jy] = *(const float4*)&sIt[r0 + jy][c];
        const float* Ap = (const float*)A;
#pragma unroll
        for (int s = 0; s < 4; s++) {
            float2 wv = *(const float2*)&sW[(c + s) * 64 + f0];
#pragma unroll
            for (int jy = 0; jy < 4; jy++) {
                acc[jy][0] += Ap[jy * 4 + s] * wv.x;
                acc[jy][1] += Ap[jy * 4 + s] * wv.y;
            }
        }
    }
#pragma unroll
    for (int jy = 0; jy < 4; jy++)
        *(float2*)&g_XW[(row0 + r0 + jy) * EDn + f0] = make_float2(acc[jy][0], acc[jy][1]);
}

// -------- per-step kernel 2: df = AnT @ XW + b ; de1/de2 = tanh(df@W +b) --------
__global__ __launch_bounds__(256) void k_df_de(const float* __restrict__ gconv_b,
                                               const float* __restrict__ w1, const float* __restrict__ b1,
                                               const float* __restrict__ w2, const float* __restrict__ b2) {
    __shared__ float dfS[32][64];
    __shared__ float uS[8192];   // phase1: aT[32][36] @0 + xwS[32][64] @1152 ; phase2: w1 @0, w2 @4096
    int b = blockIdx.y, jT = blockIdx.x;
    int tid = threadIdx.x;
    int tx = tid & 31, ty = tid >> 5;
    int f0 = tx * 2, r0 = ty * 4;

    float acc[4][2];
#pragma unroll
    for (int jy = 0; jy < 4; jy++) { acc[jy][0] = 0.f; acc[jy][1] = 0.f; }

    for (int ic = 0; ic < Nn; ic += 32) {
        for (int i = tid; i < 1024; i += 256) {
            int jj = i >> 5, ii = i & 31;
            uS[jj * 36 + ii] = g_AnT[(jT * 32 + jj) * Nn + ic + ii];
        }
        for (int i = tid; i < 2048; i += 256) {
            int ii = i >> 6, ff = i & 63;
            uS[1152 + ii * 64 + ff] = g_XW[(b * Nn + ic + ii) * EDn + ff];
        }
        __syncthreads();
#pragma unroll
        for (int ii = 0; ii < 32; ii += 4) {
            float4 A[4];
#pragma unroll
            for (int jy = 0; jy < 4; jy++) A[jy] = *(const float4*)&uS[(r0 + jy) * 36 + ii];
            const float* Ap = (const float*)A;
#pragma unroll
            for (int s = 0; s < 4; s++) {
                float2 xv = *(const float2*)&uS[1152 + (ii + s) * 64 + f0];
#pragma unroll
                for (int jy = 0; jy < 4; jy++) {
                    acc[jy][0] += Ap[jy * 4 + s] * xv.x;
                    acc[jy][1] += Ap[jy * 4 + s] * xv.y;
                }
            }
        }
        __syncthreads();
    }
    {
        float gb0 = gconv_b[f0], gb1 = gconv_b[f0 + 1];
#pragma unroll
        for (int jy = 0; jy < 4; jy++)
            *(float2*)&dfS[r0 + jy][f0] = make_float2(acc[jy][0] + gb0, acc[jy][1] + gb1);
    }
    // load both weight matrices
    for (int i = tid; i < 4096; i += 256) { uS[i] = w1[i]; uS[4096 + i] = w2[i]; }
    __syncthreads();

    float a1[4][2], a2[4][2];
#pragma unroll
    for (int jy = 0; jy < 4; jy++) { a1[jy][0] = a1[jy][1] = 0.f; a2[jy][0] = a2[jy][1] = 0.f; }
#pragma unroll 4
    for (int ff = 0; ff < 64; ff += 4) {
        float4 D[4];
#pragma unroll
        for (int jy = 0; jy < 4; jy++) D[jy] = *(const float4*)&dfS[r0 + jy][ff];
        const float* Dp = (const float*)D;
#pragma unroll
        for (int s = 0; s < 4; s++) {
            float2 w1v = *(const float2*)&uS[(ff + s) * 64 + f0];
            float2 w2v = *(const float2*)&uS[4096 + (ff + s) * 64 + f0];
#pragma unroll
            for (int jy = 0; jy < 4; jy++) {
                float dv = Dp[jy * 4 + s];
                a1[jy][0] += dv * w1v.x;  a1[jy][1] += dv * w1v.y;
                a2[jy][0] += dv * w2v.x;  a2[jy][1] += dv * w2v.y;
            }
        }
    }
    {
        float bb10 = b1[f0], bb11 = b1[f0 + 1];
        float bb20 = b2[f0], bb21 = b2[f0 + 1];
#pragma unroll
        for (int jy = 0; jy < 4; jy++) {
            int row = (b * Nn + jT * 32 + r0 + jy) * EDn;
            *(float2*)&g_de1[row + f0] = make_float2(tanhf(a1[jy][0] + bb10), tanhf(a1[jy][1] + bb11));
            *(float2*)&g_de2[row + f0] = make_float2(tanhf(a2[jy][0] + bb20), tanhf(a2[jy][1] + bb21));
        }
    }
}

// -------- per-step kernel 3: Et tiles + ring buffer + running sum + colsums --------
__device__ __forceinline__ float dot4(float4 a, float4 b) {
    return a.x * b.x + a.y * b.y + a.z * b.z + a.w * b.w;
}

__global__ __launch_bounds__(256) void k_et(int slot) {
    __shared__ float d1i[32][68], d2i[32][68], d1j[32][68], d2j[32][68];
    __shared__ float tS[32][33];
    __shared__ float colbuf[64];
    int b = blockIdx.y;
    int tid = threadIdx.x;
    int p = blockIdx.x, iT = 0;
    while (p >= 8 - iT) { p -= 8 - iT; iT++; }
    int jT = iT + p;
    bool diag = (iT == jT);

    for (int i = tid; i < 2048; i += 256) {
        int rr = i >> 6, e = i & 63;
        int gi = (b * Nn + iT * 32 + rr) * EDn + e;
        int gj = (b * Nn + jT * 32 + rr) * EDn + e;
        d1i[rr][e] = g_de1[gi];
        d2i[rr][e] = g_de2[gi];
        d1j[rr][e] = g_de1[gj];
        d2j[rr][e] = g_de2[gj];
    }
    if (tid < 64) colbuf[tid] = 0.f;
    __syncthreads();

    int tx = tid & 15, ty = tid >> 4;  // ty 0..15
    int ii0 = 2 * ty;
    int jjA = tx, jjB = tx + 16;

    float accA[2][2] = {{0.f, 0.f}, {0.f, 0.f}};
    float accB[2][2] = {{0.f, 0.f}, {0.f, 0.f}};
#pragma unroll
    for (int e = 0; e < 64; e += 4) {
        float4 P1a = *(const float4*)&d1i[ii0][e];
        float4 P1b = *(const float4*)&d1i[ii0 + 1][e];
        float4 P2a = *(const float4*)&d2i[ii0][e];
        float4 P2b = *(const float4*)&d2i[ii0 + 1][e];
        float4 QA2 = *(const float4*)&d2j[jjA][e];
        float4 QB2 = *(const float4*)&d2j[jjB][e];
        float4 QA1 = *(const float4*)&d1j[jjA][e];
        float4 QB1 = *(const float4*)&d1j[jjB][e];
        accA[0][0] += dot4(P1a, QA2);  accA[0][1] += dot4(P1a, QB2);
        accA[1][0] += dot4(P1b, QA2);  accA[1][1] += dot4(P1b, QB2);
        accB[0][0] += dot4(QA1, P2a);  accB[0][1] += dot4(QB1, P2a);
        accB[1][0] += dot4(QA1, P2b);  accB[1][1] += dot4(QB1, P2b);
    }
    float tv[2][2];
    tv[0][0] = tanhf(accA[0][0] - accB[0][0]);
    tv[0][1] = tanhf(accA[0][1] - accB[0][1]);
    tv[1][0] = tanhf(accA[1][0] - accB[1][0]);
    tv[1][1] = tanhf(accA[1][1] - accB[1][1]);

    // stage normal tile (relu applied in RMW loop)
    tS[ii0][jjA] = tv[0][0];      tS[ii0][jjB] = tv[0][1];
    tS[ii0 + 1][jjA] = tv[1][0];  tS[ii0 + 1][jjB] = tv[1][1];
    __syncthreads();

    size_t ebase = ((size_t)(b * Sn + slot) * Nn) * Nn;
    size_t mbase = ((size_t)b * Nn) * Nn;

    // RMW normal tile (iT rows, jT cols) — coalesced
#pragma unroll
    for (int q = 0; q < 4; q++) {
        int idx = tid + q * 256;
        int ii = idx >> 5, jj = idx & 31;
        int gi = iT * 32 + ii, gj = jT * 32 + jj;
        float et = fmaxf(tS[ii][jj], 0.f);
        size_t eo = ebase + (size_t)gi * Nn + gj;
        float old = g_Eh[eo];
        g_Eh[eo] = et;
        float d = et - old;
        size_t mo = mbase + (size_t)gi * Nn + gj;
        g_Msum[mo] += d;
        atomicAdd(&colbuf[jj], d);
    }

    if (!diag) {
        __syncthreads();
        // stage mirror tile: value relu(-t) at [jj][ii]
        tS[jjA][ii0] = fmaxf(-tv[0][0], 0.f);  tS[jjA][ii0 + 1] = fmaxf(-tv[1][0], 0.f);
        tS[jjB][ii0] = fmaxf(-tv[0][1], 0.f);  tS[jjB][ii0 + 1] = fmaxf(-tv[1][1], 0.f);
        __syncthreads();
#pragma unroll
        for (int q = 0; q < 4; q++) {
            int idx = tid + q * 256;
            int rr = idx >> 5, cc = idx & 31;   // row in jT range, col in iT range
            int gi = jT * 32 + rr, gj = iT * 32 + cc;
            float et = tS[rr][cc];
            size_t eo = ebase + (size_t)gi * Nn + gj;
            float old = g_Eh[eo];
            g_Eh[eo] = et;
            float d = et - old;
            size_t mo = mbase + (size_t)gi * Nn + gj;
            g_Msum[mo] += d;
            atomicAdd(&colbuf[32 + cc], d);
        }
    }
    __syncthreads();
    if (tid < 32) atomicAdd(&g_colsum[b * Nn + jT * 32 + tid], colbuf[tid]);
    if (!diag && tid >= 32 && tid < 64)
        atomicAdd(&g_colsum[b * Nn + iT * 32 + (tid - 32)], colbuf[tid]);
}

// -------- per-step kernel 4: s-reduction + fused GRU update --------
__global__ __launch_bounds__(256) void k_gru(const float* __restrict__ x,
                                             const float* __restrict__ wz_l, const float* __restrict__ bz_l,
                                             const float* __restrict__ wr_l, const float* __restrict__ br_l,
                                             const float* __restrict__ wh_l, const float* __restrict__ bh_l,
                                             int t, float cnt) {
    __shared__ float dinvS[256];
    __shared__ float dxv[256];
    __shared__ float part[8][32];
    __shared__ float sS[32];
    __shared__ float hS[32][64];
    __shared__ float hrS[32][64];
    __shared__ float wS[4096];

    int b = blockIdx.y;
    int n0 = blockIdx.x * 32;
    int tid = threadIdx.x;
    float inv_cnt = 1.0f / cnt;

    {
        int i = tid;
        float cs = g_colsum[b * Nn + i];
        float dv = 1.0f / sqrtf(cs * inv_cnt + 1.0f);
        dinvS[i] = dv;
        dxv[i] = dv * x[(b * Nn + i) * Tn + t];
    }
    for (int i = tid; i < 2048; i += 256) {
        int rr = i >> 6, ff = i & 63;
        hS[rr][ff] = g_h[(b * Nn + n0 + rr) * Hn + ff];
    }
    __syncthreads();

    {
        int c = tid & 31, g = tid >> 5;
        float acc = 0.f;
        int ibase = g * 32;
#pragma unroll 8
        for (int k = 0; k < 32; k++) {
            int i = ibase + k;
            acc += g_Msum[((size_t)b * Nn + i) * Nn + n0 + c] * dxv[i];
        }
        part[g][c] = acc;
    }
    __syncthreads();
    if (tid < 32) {
        float sraw = 0.f;
#pragma unroll
        for (int g = 0; g < 8; g++) sraw += part[g][tid];
        int n = n0 + tid;
        float dj = dinvS[n];
        sS[tid] = dj * (sraw * inv_cnt + dj * x[(b * Nn + n) * Tn + t]);
    }
    for (int i = tid; i < 4096; i += 256) wS[i] = wz_l[(Hn + (i >> 6)) * Hn + (i & 63)];
    __syncthreads();

    int tx = tid & 31, ty = tid >> 5;
    int f0 = tx * 2, r0 = ty * 4;
    float z[4][2];

    // ---- z gate ----
    {
        float c0 = g_coef[f0], c1 = g_coef[f0 + 1];
        float d0 = g_coef[64 + f0], d1 = g_coef[64 + f0 + 1];
        float bz0 = bz_l[f0], bz1 = bz_l[f0 + 1];
        float acc[4][2];
#pragma unroll
        for (int jy = 0; jy < 4; jy++) {
            float s = sS[r0 + jy];
            acc[jy][0] = s * c0 + d0 + bz0;
            acc[jy][1] = s * c1 + d1 + bz1;
        }
#pragma unroll 4
        for (int ff = 0; ff < 64; ff += 4) {
            float4 Hq[4];
#pragma unroll
            for (int jy = 0; jy < 4; jy++) Hq[jy] = *(const float4*)&hS[r0 + jy][ff];
            const float* Hp = (const float*)Hq;
#pragma unroll
            for (int s = 0; s < 4; s++) {
                float2 wv = *(const float2*)&wS[(ff + s) * 64 + f0];
#pragma unroll
                for (int jy = 0; jy < 4; jy++) {
                    acc[jy][0] += Hp[jy * 4 + s] * wv.x;
                    acc[jy][1] += Hp[jy * 4 + s] * wv.y;
                }
            }
        }
#pragma unroll
        for (int jy = 0; jy < 4; jy++) {
            z[jy][0] = 1.0f / (1.0f + expf(-acc[jy][0]));
            z[jy][1] = 1.0f / (1.0f + expf(-acc[jy][1]));
        }
    }
    __syncthreads();
    for (int i = tid; i < 4096; i += 256) wS[i] = wr_l[(Hn + (i >> 6)) * Hn + (i & 63)];
    __syncthreads();

    // ---- r gate -> hr ----
    {
        float c0 = g_coef[128 + f0], c1 = g_coef[128 + f0 + 1];
        float d0 = g_coef[192 + f0], d1 = g_coef[192 + f0 + 1];
        float br0 = br_l[f0], br1 = br_l[f0 + 1];
        float acc[4][2];
#pragma unroll
        for (int jy = 0; jy < 4; jy++) {
            float s = sS[r0 + jy];
            acc[jy][0] = s * c0 + d0 + br0;
            acc[jy][1] = s * c1 + d1 + br1;
        }
#pragma unroll 4
        for (int ff = 0; ff < 64; ff += 4) {
            float4 Hq[4];
#pragma unroll
            for (int jy = 0; jy < 4; jy++) Hq[jy] = *(const float4*)&hS[r0 + jy][ff];
            const float* Hp = (const float*)Hq;
#pragma unroll
            for (int s = 0; s < 4; s++) {
                float2 wv = *(const float2*)&wS[(ff + s) * 64 + f0];
#pragma unroll
                for (int jy = 0; jy < 4; jy++) {
                    acc[jy][0] += Hp[jy * 4 + s] * wv.x;
                    acc[jy][1] += Hp[jy * 4 + s] * wv.y;
                }
            }
        }
#pragma unroll
        for (int jy = 0; jy < 4; jy++) {
            float r0v = 1.0f / (1.0f + expf(-acc[jy][0]));
            float r1v = 1.0f / (1.0f + expf(-acc[jy][1]));
            float2 hv = *(const float2*)&hS[r0 + jy][f0];
            *(float2*)&hrS[r0 + jy][f0] = make_float2(hv.x * r0v, hv.y * r1v);
        }
    }
    __syncthreads();
    for (int i = tid; i < 4096; i += 256) wS[i] = wh_l[(Hn + (i >> 6)) * Hn + (i & 63)];
    __syncthreads();

    // ---- h candidate + combine ----
    {
        float c0 = g_coef[256 + f0], c1 = g_coef[256 + f0 + 1];
        float d0 = g_coef[320 + f0], d1 = g_coef[320 + f0 + 1];
        float bh0 = bh_l[f0], bh1 = bh_l[f0 + 1];
        float acc[4][2];
#pragma unroll
        for (int jy = 0; jy < 4; jy++) {
            float s = sS[r0 + jy];
            acc[jy][0] = s * c0 + d0 + bh0;
            acc[jy][1] = s * c1 + d1 + bh1;
        }
#pragma unroll 4
        for (int ff = 0; ff < 64; ff += 4) {
            float4 Hq[4];
#pragma unroll
            for (int jy = 0; jy < 4; jy++) Hq[jy] = *(const float4*)&hrS[r0 + jy][ff];
            const float* Hp = (const float*)Hq;
#pragma unroll
            for (int s = 0; s < 4; s++) {
                float2 wv = *(const float2*)&wS[(ff + s) * 64 + f0];
#pragma unroll
                for (int jy = 0; jy < 4; jy++) {
                    acc[jy][0] += Hp[jy * 4 + s] * wv.x;
                    acc[jy][1] += Hp[jy * 4 + s] * wv.y;
                }
            }
        }
#pragma unroll
        for (int jy = 0; jy < 4; jy++) {
            float ht0 = tanhf(acc[jy][0]);
            float ht1 = tanhf(acc[jy][1]);
            float2 hv = *(const float2*)&hS[r0 + jy][f0];
            float hn0 = z[jy][0] * hv.x + (1.0f - z[jy][0]) * ht0;
            float hn1 = z[jy][1] * hv.y + (1.0f - z[jy][1]) * ht1;
            *(float2*)&g_h[(b * Nn + n0 + r0 + jy) * Hn + f0] = make_float2(hn0, hn1);
        }
    }
}

// ---------------- final classifier ----------------
__global__ __launch_bounds__(256) void k_cls(const float* __restrict__ cls_w,
                                             const float* __restrict__ cls_b,
                                             float* __restrict__ out) {
    int b = blockIdx.x, tid = threadIdx.x;
    float acc[4] = {0.f, 0.f, 0.f, 0.f};
    for (int i = tid; i < Nn * Hn; i += 256) {
        float hv = g_h[b * Nn * Hn + i];
#pragma unroll
        for (int c = 0; c < 4; c++) acc[c] += hv * cls_w[i * Cn + c];
    }
    __shared__ float red[4][256];
#pragma unroll
    for (int c = 0; c < 4; c++) red[c][tid] = acc[c];
    __syncthreads();
    for (int s = 128; s > 0; s >>= 1) {
        if (tid < s) {
#pragma unroll
            for (int c = 0; c < 4; c++) red[c][tid] += red[c][tid + s];
        }
        __syncthreads();
    }
    if (tid < 4) out[b * Cn + tid] = red[tid][0] + cls_b[tid];
}

// ---------------- launch ----------------
extern "C" void kernel_launch(void* const* d_in, const int* in_sizes, int n_in,
                              void* d_out, int out_size) {
    const float* x        = (const float*)d_in[0];
    const float* ew       = (const float*)d_in[1];
    const float* gconv_w  = (const float*)d_in[2];
    const float* gconv_b  = (const float*)d_in[3];
    const float* w1       = (const float*)d_in[4];
    const float* b1       = (const float*)d_in[5];
    const float* w2       = (const float*)d_in[6];
    const float* b2       = (const float*)d_in[7];
    const float* wz_c     = (const float*)d_in[8];
    const float* bz_c     = (const float*)d_in[9];
    const float* wz_l     = (const float*)d_in[10];
    const float* bz_l     = (const float*)d_in[11];
    const float* wr_c     = (const float*)d_in[12];
    const float* br_c     = (const float*)d_in[13];
    const float* wr_l     = (const float*)d_in[14];
    const float* br_l     = (const float*)d_in[15];
    const float* wh_c     = (const float*)d_in[16];
    const float* bh_c     = (const float*)d_in[17];
    const float* wh_l     = (const float*)d_in[18];
    const float* bh_l     = (const float*)d_in[19];
    const float* cls_w    = (const float*)d_in[20];
    const float* cls_b    = (const float*)d_in[21];
    const int*   eidx     = (const int*)d_in[22];
    float* out = (float*)d_out;

    k_zero<<<2048, 256>>>();
    k_scatter<<<(En + 255) / 256, 256>>>(eidx, ew);
    k_statdeg<<<1, 256>>>();
    k_statAnT<<<(Nn * Nn + 255) / 256, 256>>>();
    k_precoef<<<1, 64>>>(wz_c, wz_l, bz_c, wr_c, wr_l, br_c, wh_c, wh_l, bh_c);

    for (int t = 0; t < Tn; t++) {
        int slot = t % Sn;
        float cnt = (float)((t + 1 < Sn) ? (t + 1) : Sn);
        k_xw<<<Bn * Nn / 32, 256>>>(x, gconv_w, t);
        k_df_de<<<dim3(8, Bn), 256>>>(gconv_b, w1, b1, w2, b2);
        k_et<<<dim3(36, Bn), 256>>>(slot);
        k_gru<<<dim3(8, Bn), 256>>>(x, wz_l, bz_l, wr_l, br_l, wh_l, bh_l, t, cnt);
    }

    k_cls<<<Bn, 256>>>(cls_w, cls_b, out);
}

// round 8
// speedup vs baseline: 1.6656x; 1.1236x over previous
#include <cuda_runtime.h>
#include <math.h>

#define Bn 16
#define Nn 256
#define Tn 64
#define Wn 12
#define Hn 64
#define EDn 64
#define Sn 5
#define Cn 4
#define En 2048
#define FGn 76   // W + H
#define CAP 64   // max in-degree capacity (E/N avg = 8, Poisson tail << 64)

typedef unsigned long long ull;

// ---------------- f32x2 packed-FMA helpers (sm_103a FFMA2) ----------------
__device__ __forceinline__ void fma2(ull& d, ull a, ull b) {
    asm("fma.rn.f32x2 %0, %1, %2, %0;" : "+l"(d) : "l"(a), "l"(b));
}
__device__ __forceinline__ ull splat2(float v) {
    ull r; asm("mov.b64 %0, {%1, %1};" : "=l"(r) : "f"(v)); return r;
}
__device__ __forceinline__ ull pack2(float lo, float hi) {
    ull r; asm("mov.b64 %0, {%1, %2};" : "=l"(r) : "f"(lo), "f"(hi)); return r;
}
__device__ __forceinline__ float2 unpack2(ull v) {
    float lo, hi; asm("mov.b64 {%0, %1}, %2;" : "=f"(lo), "=f"(hi) : "l"(v));
    return make_float2(lo, hi);
}
__device__ __forceinline__ float hadd2(ull v) { float2 f = unpack2(v); return f.x + f.y; }

// ---------------- device scratch (no allocation allowed) ----------------
__device__ float g_dinv_stat[Nn];
__device__ int   g_nbr_cnt[Nn];
__device__ int   g_nbr_idx[Nn * CAP];
__device__ float g_nbr_w[Nn * CAP];
__device__ float g_coef[6 * Hn];               // az, cz0, ar, cr0, ah, ch0
__device__ float g_XW[Bn * Nn * EDn];
__device__ float g_de1[Bn * Nn * EDn];
__device__ float g_de2[Bn * Nn * EDn];
__device__ float g_Eh[(size_t)Bn * Sn * Nn * Nn];   // ring buffer of Et
__device__ float g_Msum[(size_t)Bn * Nn * Nn];      // running sum over ring slots
__device__ float g_colsum[Bn * Nn];                 // column sums of Msum
__device__ float g_h[Bn * Nn * Hn];

// ---------------- setup kernels ----------------
__global__ void k_zero() {
    size_t idx = (size_t)blockIdx.x * blockDim.x + threadIdx.x;
    size_t str = (size_t)gridDim.x * blockDim.x;
    for (size_t i = idx; i < (size_t)Bn * Sn * Nn * Nn; i += str) g_Eh[i] = 0.f;
    for (size_t i = idx; i < (size_t)Bn * Nn * Nn; i += str) g_Msum[i] = 0.f;
    for (size_t i = idx; i < (size_t)Bn * Nn; i += str) g_colsum[i] = 0.f;
    for (size_t i = idx; i < (size_t)Bn * Nn * Hn; i += str) g_h[i] = 0.f;
}

// Deterministic adjacency-list build: thread j scans all edges in order.
__global__ void k_build(const int* __restrict__ ei, const float* __restrict__ ew) {
    int j = threadIdx.x;  // 256 threads, 1 block
    float deg = 1.0f;     // self loop
    for (int e = 0; e < En; e++)
        if (ei[En + e] == j) deg += ew[e];
    g_dinv_stat[j] = 1.0f / sqrtf(deg);
    __syncthreads();
    float dj = g_dinv_stat[j];
    int cnt = 1;
    g_nbr_idx[j * CAP] = j;
    g_nbr_w[j * CAP] = dj * dj;       // self-loop: dinv[j]*1*dinv[j]
    for (int e = 0; e < En; e++) {
        if (ei[En + e] == j && cnt < CAP) {
            int s = ei[e];
            g_nbr_idx[j * CAP + cnt] = s;
            g_nbr_w[j * CAP + cnt] = g_dinv_stat[s] * ew[e] * dj;
            cnt++;
        }
    }
    g_nbr_cnt[j] = cnt;
}

__global__ void k_precoef(const float* wz_c, const float* wz_l, const float* bz_c,
                          const float* wr_c, const float* wr_l, const float* br_c,
                          const float* wh_c, const float* wh_l, const float* bh_c) {
    int k = threadIdx.x;  // 64 threads
    float az = 0, cz = 0, ar = 0, cr = 0, ah = 0, ch = 0;
    for (int f = 0; f < Hn; f++) {
        float wzl = wz_l[f * Hn + k], wrl = wr_l[f * Hn + k], whl = wh_l[f * Hn + k];
        az += wz_c[f] * wzl;  cz += bz_c[f] * wzl;
        ar += wr_c[f] * wrl;  cr += br_c[f] * wrl;
        ah += wh_c[f] * whl;  ch += bh_c[f] * whl;
    }
    g_coef[k] = az;        g_coef[64 + k] = cz;
    g_coef[128 + k] = ar;  g_coef[192 + k] = cr;
    g_coef[256 + k] = ah;  g_coef[320 + k] = ch;
}

// ---------------- initial XW (t=0 only; h=0) ----------------
__global__ __launch_bounds__(256) void k_xw(const float* __restrict__ x,
                                            const float* __restrict__ Wg, int t) {
    __shared__ float sW[FGn * EDn];
    __shared__ float sIt[32][80];
    int tid = threadIdx.x;
    for (int i = tid; i < FGn * EDn; i += 256) sW[i] = Wg[i];
    int row0 = blockIdx.x * 32;
    for (int i = tid; i < 32 * FGn; i += 256) {
        int rr = i / FGn, c = i - rr * FGn;
        int row = row0 + rr;
        float v;
        if (c < Wn) {
            int tt = t + c - (Wn - 1);
            v = (tt >= 0) ? x[row * Tn + tt] : 0.0f;
        } else {
            v = g_h[row * Hn + (c - Wn)];
        }
        sIt[rr][c] = v;
    }
    __syncthreads();
    int tx = tid & 31, ty = tid >> 5;
    int f0 = tx * 2, r0 = ty * 4;
    ull acc[4];
#pragma unroll
    for (int jy = 0; jy < 4; jy++) acc[jy] = 0ull;
#pragma unroll 4
    for (int c = 0; c < FGn; c++) {
        ull wv = *(const ull*)&sW[c * 64 + f0];
#pragma unroll
        for (int jy = 0; jy < 4; jy++) fma2(acc[jy], splat2(sIt[r0 + jy][c]), wv);
    }
#pragma unroll
    for (int jy = 0; jy < 4; jy++) {
        float2 r = unpack2(acc[jy]);
        *(float2*)&g_XW[(row0 + r0 + jy) * EDn + f0] = r;
    }
}

// -------- per-step kernel A: df (sparse gather) + de1/de2 GEMMs --------
__global__ __launch_bounds__(256) void k_df_de(const float* __restrict__ gconv_b,
                                               const float* __restrict__ w1, const float* __restrict__ b1,
                                               const float* __restrict__ w2, const float* __restrict__ b2) {
    __shared__ float dfS[32][64];
    __shared__ float wS[8192];   // w1 @0, w2 @4096
    int b = blockIdx.y, jT = blockIdx.x;
    int tid = threadIdx.x;

    // phase 1: sparse gather df[j][f] = sum_k w_k * XW[i_k][f] + gconv_b[f]
    {
        int f = tid & 63, jg = tid >> 6;
        float gb = gconv_b[f];
#pragma unroll
        for (int q = 0; q < 8; q++) {
            int jl = jg + q * 4;
            int j = jT * 32 + jl;
            int cnt = g_nbr_cnt[j];
            float acc = 0.f;
            for (int k = 0; k < cnt; k++) {
                int i = g_nbr_idx[j * CAP + k];
                float w = g_nbr_w[j * CAP + k];
                acc += w * g_XW[(b * Nn + i) * EDn + f];
            }
            dfS[jl][f] = acc + gb;
        }
    }
    for (int i = tid; i < 4096; i += 256) { wS[i] = w1[i]; wS[4096 + i] = w2[i]; }
    __syncthreads();

    // phase 2: de1/de2 = tanh(df @ W + b), packed f32x2
    int tx = tid & 31, ty = tid >> 5;
    int f0 = tx * 2, r0 = ty * 4;
    ull a1[4], a2[4];
#pragma unroll
    for (int jy = 0; jy < 4; jy++) { a1[jy] = 0ull; a2[jy] = 0ull; }
#pragma unroll 4
    for (int ff = 0; ff < 64; ff += 4) {
        float4 D[4];
#pragma unroll
        for (int jy = 0; jy < 4; jy++) D[jy] = *(const float4*)&dfS[r0 + jy][ff];
        const float* Dp = (const float*)D;
#pragma unroll
        for (int s = 0; s < 4; s++) {
            ull w1v = *(const ull*)&wS[(ff + s) * 64 + f0];
            ull w2v = *(const ull*)&wS[4096 + (ff + s) * 64 + f0];
#pragma unroll
            for (int jy = 0; jy < 4; jy++) {
                ull dv = splat2(Dp[jy * 4 + s]);
                fma2(a1[jy], dv, w1v);
                fma2(a2[jy], dv, w2v);
            }
        }
    }
    {
        float bb10 = b1[f0], bb11 = b1[f0 + 1];
        float bb20 = b2[f0], bb21 = b2[f0 + 1];
#pragma unroll
        for (int jy = 0; jy < 4; jy++) {
            int row = (b * Nn + jT * 32 + r0 + jy) * EDn;
            float2 v1 = unpack2(a1[jy]);
            float2 v2 = unpack2(a2[jy]);
            *(float2*)&g_de1[row + f0] = make_float2(tanhf(v1.x + bb10), tanhf(v1.y + bb11));
            *(float2*)&g_de2[row + f0] = make_float2(tanhf(v2.x + bb20), tanhf(v2.y + bb21));
        }
    }
}

// -------- per-step kernel B: Et tiles + ring buffer + running sum + colsums --------
__global__ __launch_bounds__(128) void k_et(int slot) {
    __shared__ float d1i[32][68], d2i[32][68], d1j[32][68], d2j[32][68];
    __shared__ float tS[32][33];
    __shared__ float colbuf[64];
    int b = blockIdx.y;
    int tid = threadIdx.x;   // 128 threads
    int p = blockIdx.x, iT = 0;
    while (p >= 8 - iT) { p -= 8 - iT; iT++; }
    int jT = iT + p;
    bool diag = (iT == jT);

    for (int i = tid; i < 2048; i += 128) {
        int rr = i >> 6, e = i & 63;
        int gi = (b * Nn + iT * 32 + rr) * EDn + e;
        int gj = (b * Nn + jT * 32 + rr) * EDn + e;
        d1i[rr][e] = g_de1[gi];
        d2i[rr][e] = g_de2[gi];
        d1j[rr][e] = g_de1[gj];
        d2j[rr][e] = g_de2[gj];
    }
    if (tid < 64) colbuf[tid] = 0.f;
    __syncthreads();

    // thread cells: ii = ty + 16a (a=0..1), jj = tx + 8c (c=0..3) — strided,
    // conflict-free (8 distinct 16B chunks tile all banks, ty/tx broadcast dedup)
    int tx = tid & 7, ty = tid >> 3;   // ty 0..15
    ull accA[2][4], accB[4][2];
#pragma unroll
    for (int a = 0; a < 2; a++)
#pragma unroll
        for (int c = 0; c < 4; c++) { accA[a][c] = 0ull; accB[c][a] = 0ull; }

#pragma unroll
    for (int e0 = 0; e0 < 64; e0 += 4) {
        ulonglong2 P1[2], P2[2], Q1[4], Q2[4];
#pragma unroll
        for (int a = 0; a < 2; a++) {
            P1[a] = *(const ulonglong2*)&d1i[ty + 16 * a][e0];
            P2[a] = *(const ulonglong2*)&d2i[ty + 16 * a][e0];
        }
#pragma unroll
        for (int c = 0; c < 4; c++) {
            Q1[c] = *(const ulonglong2*)&d1j[tx + 8 * c][e0];
            Q2[c] = *(const ulonglong2*)&d2j[tx + 8 * c][e0];
        }
#pragma unroll
        for (int a = 0; a < 2; a++)
#pragma unroll
            for (int c = 0; c < 4; c++) {
                fma2(accA[a][c], P1[a].x, Q2[c].x);
                fma2(accA[a][c], P1[a].y, Q2[c].y);
                fma2(accB[c][a], Q1[c].x, P2[a].x);
                fma2(accB[c][a], Q1[c].y, P2[a].y);
            }
    }
    float tv[2][4];
#pragma unroll
    for (int a = 0; a < 2; a++)
#pragma unroll
        for (int c = 0; c < 4; c++) {
            tv[a][c] = tanhf(hadd2(accA[a][c]) - hadd2(accB[c][a]));
            tS[ty + 16 * a][tx + 8 * c] = tv[a][c];
        }
    __syncthreads();

    size_t ebase = ((size_t)(b * Sn + slot) * Nn) * Nn;
    size_t mbase = ((size_t)b * Nn) * Nn;

    // RMW normal tile (iT rows, jT cols) — coalesced
#pragma unroll
    for (int q = 0; q < 8; q++) {
        int idx = tid + q * 128;
        int ii = idx >> 5, jj = idx & 31;
        int gi = iT * 32 + ii, gj = jT * 32 + jj;
        float et = fmaxf(tS[ii][jj], 0.f);
        size_t eo = ebase + (size_t)gi * Nn + gj;
        float old = g_Eh[eo];
        g_Eh[eo] = et;
        float d = et - old;
        g_Msum[mbase + (size_t)gi * Nn + gj] += d;
        atomicAdd(&colbuf[jj], d);
    }

    if (!diag) {
        __syncthreads();
#pragma unroll
        for (int a = 0; a < 2; a++)
#pragma unroll
            for (int c = 0; c < 4; c++)
                tS[tx + 8 * c][ty + 16 * a] = fmaxf(-tv[a][c], 0.f);
        __syncthreads();
#pragma unroll
        for (int q = 0; q < 8; q++) {
            int idx = tid + q * 128;
            int rr = idx >> 5, cc = idx & 31;  // row in jT range, col in iT range
            int gi = jT * 32 + rr, gj = iT * 32 + cc;
            float et = tS[rr][cc];
            size_t eo = ebase + (size_t)gi * Nn + gj;
            float old = g_Eh[eo];
            g_Eh[eo] = et;
            float d = et - old;
            g_Msum[mbase + (size_t)gi * Nn + gj] += d;
            atomicAdd(&colbuf[32 + cc], d);
        }
    }
    __syncthreads();
    if (tid < 32) atomicAdd(&g_colsum[b * Nn + jT * 32 + tid], colbuf[tid]);
    if (!diag && tid >= 32 && tid < 64)
        atomicAdd(&g_colsum[b * Nn + iT * 32 + (tid - 32)], colbuf[tid]);
}

// -------- per-step kernel C: s-reduction + fused GRU update + next-step XW --------
__global__ __launch_bounds__(256) void k_gru(const float* __restrict__ x,
                                             const float* __restrict__ Wg,
                                             const float* __restrict__ wz_l, const float* __restrict__ bz_l,
                                             const float* __restrict__ wr_l, const float* __restrict__ br_l,
                                             const float* __restrict__ wh_l, const float* __restrict__ bh_l,
                                             int t, float cnt) {
    __shared__ float dinvS[256];
    __shared__ float dxv[256];
    __shared__ float part[8][32];
    __shared__ float sS[32];
    __shared__ float hS[32][64];
    __shared__ float hrS[32][64];       // later holds h_new
    __shared__ float wS[FGn * 64];      // gates use [0,4096); XW uses all 4864
    __shared__ float sIt[32][12];

    int b = blockIdx.y;
    int n0 = blockIdx.x * 32;
    int tid = threadIdx.x;
    float inv_cnt = 1.0f / cnt;

    {
        int i = tid;
        float cs = g_colsum[b * Nn + i];
        float dv = 1.0f / sqrtf(cs * inv_cnt + 1.0f);
        dinvS[i] = dv;
        dxv[i] = dv * x[(b * Nn + i) * Tn + t];
    }
    for (int i = tid; i < 2048; i += 256) {
        int rr = i >> 6, ff = i & 63;
        hS[rr][ff] = g_h[(b * Nn + n0 + rr) * Hn + ff];
    }
    __syncthreads();

    {
        int c = tid & 31, g = tid >> 5;
        float acc = 0.f;
        int ibase = g * 32;
#pragma unroll 8
        for (int k = 0; k < 32; k++) {
            int i = ibase + k;
            acc += g_Msum[((size_t)b * Nn + i) * Nn + n0 + c] * dxv[i];
        }
        part[g][c] = acc;
    }
    __syncthreads();
    if (tid < 32) {
        float sraw = 0.f;
#pragma unroll
        for (int g = 0; g < 8; g++) sraw += part[g][tid];
        int n = n0 + tid;
        float dj = dinvS[n];
        sS[tid] = dj * (sraw * inv_cnt + dj * x[(b * Nn + n) * Tn + t]);
    }
    for (int i = tid; i < 4096; i += 256) wS[i] = wz_l[(Hn + (i >> 6)) * Hn + (i & 63)];
    __syncthreads();

    int tx = tid & 31, ty = tid >> 5;
    int f0 = tx * 2, r0 = ty * 4;
    float2 z[4];

    // ---- z gate ----
    {
        float c0 = g_coef[f0], c1 = g_coef[f0 + 1];
        float d0 = g_coef[64 + f0], d1 = g_coef[64 + f0 + 1];
        float bz0 = bz_l[f0], bz1 = bz_l[f0 + 1];
        ull acc[4];
#pragma unroll
        for (int jy = 0; jy < 4; jy++) {
            float s = sS[r0 + jy];
            acc[jy] = pack2(s * c0 + d0 + bz0, s * c1 + d1 + bz1);
        }
#pragma unroll 4
        for (int ff = 0; ff < 64; ff += 4) {
            float4 Hq[4];
#pragma unroll
            for (int jy = 0; jy < 4; jy++) Hq[jy] = *(const float4*)&hS[r0 + jy][ff];
            const float* Hp = (const float*)Hq;
#pragma unroll
            for (int s = 0; s < 4; s++) {
                ull wv = *(const ull*)&wS[(ff + s) * 64 + f0];
#pragma unroll
                for (int jy = 0; jy < 4; jy++) fma2(acc[jy], splat2(Hp[jy * 4 + s]), wv);
            }
        }
#pragma unroll
        for (int jy = 0; jy < 4; jy++) {
            float2 a = unpack2(acc[jy]);
            z[jy] = make_float2(1.0f / (1.0f + expf(-a.x)), 1.0f / (1.0f + expf(-a.y)));
        }
    }
    __syncthreads();
    for (int i = tid; i < 4096; i += 256) wS[i] = wr_l[(Hn + (i >> 6)) * Hn + (i & 63)];
    __syncthreads();

    // ---- r gate -> hr ----
    {
        float c0 = g_coef[128 + f0], c1 = g_coef[128 + f0 + 1];
        float d0 = g_coef[192 + f0], d1 = g_coef[192 + f0 + 1];
        float br0 = br_l[f0], br1 = br_l[f0 + 1];
        ull acc[4];
#pragma unroll
        for (int jy = 0; jy < 4; jy++) {
            float s = sS[r0 + jy];
            acc[jy] = pack2(s * c0 + d0 + br0, s * c1 + d1 + br1);
        }
#pragma unroll 4
        for (int ff = 0; ff < 64; ff += 4) {
            float4 Hq[4];
#pragma unroll
            for (int jy = 0; jy < 4; jy++) Hq[jy] = *(const float4*)&hS[r0 + jy][ff];
            const float* Hp = (const float*)Hq;
#pragma unroll
            for (int s = 0; s < 4; s++) {
                ull wv = *(const ull*)&wS[(ff + s) * 64 + f0];
#pragma unroll
                for (int jy = 0; jy < 4; jy++) fma2(acc[jy], splat2(Hp[jy * 4 + s]), wv);
            }
        }
#pragma unroll
        for (int jy = 0; jy < 4; jy++) {
            float2 a = unpack2(acc[jy]);
            float rv0 = 1.0f / (1.0f + expf(-a.x));
            float rv1 = 1.0f / (1.0f + expf(-a.y));
            float2 hv = *(const float2*)&hS[r0 + jy][f0];
            *(float2*)&hrS[r0 + jy][f0] = make_float2(hv.x * rv0, hv.y * rv1);
        }
    }
    __syncthreads();
    for (int i = tid; i < 4096; i += 256) wS[i] = wh_l[(Hn + (i >> 6)) * Hn + (i & 63)];
    __syncthreads();

    // ---- h candidate + combine ----
    {
        float c0 = g_coef[256 + f0], c1 = g_coef[256 + f0 + 1];
        float d0 = g_coef[320 + f0], d1 = g_coef[320 + f0 + 1];
        float bh0 = bh_l[f0], bh1 = bh_l[f0 + 1];
        ull acc[4];
#pragma unroll
        for (int jy = 0; jy < 4; jy++) {
            float s = sS[r0 + jy];
            acc[jy] = pack2(s * c0 + d0 + bh0, s * c1 + d1 + bh1);
        }
#pragma unroll 4
        for (int ff = 0; ff < 64; ff += 4) {
            float4 Hq[4];
#pragma unroll
            for (int jy = 0; jy < 4; jy++) Hq[jy] = *(const float4*)&hrS[r0 + jy][ff];
            const float* Hp = (const float*)Hq;
#pragma unroll
            for (int s = 0; s < 4; s++) {
                ull wv = *(const ull*)&wS[(ff + s) * 64 + f0];
#pragma unroll
                for (int jy = 0; jy < 4; jy++) fma2(acc[jy], splat2(Hp[jy * 4 + s]), wv);
            }
        }
        __syncwarp();   // hrS rows are warp-private; ensure all lanes done reading
#pragma unroll
        for (int jy = 0; jy < 4; jy++) {
            float2 a = unpack2(acc[jy]);
            float ht0 = tanhf(a.x);
            float ht1 = tanhf(a.y);
            float2 hv = *(const float2*)&hS[r0 + jy][f0];
            float hn0 = z[jy].x * hv.x + (1.0f - z[jy].x) * ht0;
            float hn1 = z[jy].y * hv.y + (1.0f - z[jy].y) * ht1;
            *(float2*)&g_h[(b * Nn + n0 + r0 + jy) * Hn + f0] = make_float2(hn0, hn1);
            *(float2*)&hrS[r0 + jy][f0] = make_float2(hn0, hn1);   // h_new for XW
        }
    }

    // ---- fused next-step XW (skip on last step) ----
    if (t == Tn - 1) return;
    __syncthreads();
    for (int i = tid; i < FGn * 64; i += 256) wS[i] = Wg[i];
    for (int i = tid; i < 32 * Wn; i += 256) {
        int rr = i / Wn, c = i - rr * Wn;
        int tt = t + 1 + c - (Wn - 1);
        sIt[rr][c] = (tt >= 0) ? x[(b * Nn + n0 + rr) * Tn + tt] : 0.0f;
    }
    __syncthreads();
    {
        ull acc[4];
#pragma unroll
        for (int jy = 0; jy < 4; jy++) acc[jy] = 0ull;
#pragma unroll
        for (int c = 0; c < Wn; c++) {
            ull wv = *(const ull*)&wS[c * 64 + f0];
#pragma unroll
            for (int jy = 0; jy < 4; jy++) fma2(acc[jy], splat2(sIt[r0 + jy][c]), wv);
        }
#pragma unroll 4
        for (int c = 0; c < Hn; c++) {
            ull wv = *(const ull*)&wS[(Wn + c) * 64 + f0];
#pragma unroll
            for (int jy = 0; jy < 4; jy++) fma2(acc[jy], splat2(hrS[r0 + jy][c]), wv);
        }
#pragma unroll
        for (int jy = 0; jy < 4; jy++) {
            float2 r = unpack2(acc[jy]);
            *(float2*)&g_XW[(b * Nn + n0 + r0 + jy) * EDn + f0] = r;
        }
    }
}

// ---------------- final classifier ----------------
__global__ __launch_bounds__(256) void k_cls(const float* __restrict__ cls_w,
                                             const float* __restrict__ cls_b,
                                             float* __restrict__ out) {
    int b = blockIdx.x, tid = threadIdx.x;
    float acc[4] = {0.f, 0.f, 0.f, 0.f};
    for (int i = tid; i < Nn * Hn; i += 256) {
        float hv = g_h[b * Nn * Hn + i];
#pragma unroll
        for (int c = 0; c < 4; c++) acc[c] += hv * cls_w[i * Cn + c];
    }
    __shared__ float red[4][256];
#pragma unroll
    for (int c = 0; c < 4; c++) red[c][tid] = acc[c];
    __syncthreads();
    for (int s = 128; s > 0; s >>= 1) {
        if (tid < s) {
#pragma unroll
            for (int c = 0; c < 4; c++) red[c][tid] += red[c][tid + s];
        }
        __syncthreads();
    }
    if (tid < 4) out[b * Cn + tid] = red[tid][0] + cls_b[tid];
}

// ---------------- launch ----------------
extern "C" void kernel_launch(void* const* d_in, const int* in_sizes, int n_in,
                              void* d_out, int out_size) {
    const float* x        = (const float*)d_in[0];
    const float* ew       = (const float*)d_in[1];
    const float* gconv_w  = (const float*)d_in[2];
    const float* gconv_b  = (const float*)d_in[3];
    const float* w1       = (const float*)d_in[4];
    const float* b1       = (const float*)d_in[5];
    const float* w2       = (const float*)d_in[6];
    const float* b2       = (const float*)d_in[7];
    const float* wz_c     = (const float*)d_in[8];
    const float* bz_c     = (const float*)d_in[9];
    const float* wz_l     = (const float*)d_in[10];
    const float* bz_l     = (const float*)d_in[11];
    const float* wr_c     = (const float*)d_in[12];
    const float* br_c     = (const float*)d_in[13];
    const float* wr_l     = (const float*)d_in[14];
    const float* br_l     = (const float*)d_in[15];
    const float* wh_c     = (const float*)d_in[16];
    const float* bh_c     = (const float*)d_in[17];
    const float* wh_l     = (const float*)d_in[18];
    const float* bh_l     = (const float*)d_in[19];
    const float* cls_w    = (const float*)d_in[20];
    const float* cls_b    = (const float*)d_in[21];
    const int*   eidx     = (const int*)d_in[22];
    float* out = (float*)d_out;

    k_zero<<<2048, 256>>>();
    k_build<<<1, 256>>>(eidx, ew);
    k_precoef<<<1, 64>>>(wz_c, wz_l, bz_c, wr_c, wr_l, br_c, wh_c, wh_l, bh_c);
    k_xw<<<Bn * Nn / 32, 256>>>(x, gconv_w, 0);

    for (int t = 0; t < Tn; t++) {
        int slot = t % Sn;
        float cnt = (float)((t + 1 < Sn) ? (t + 1) : Sn);
        k_df_de<<<dim3(8, Bn), 256>>>(gconv_b, w1, b1, w2, b2);
        k_et<<<dim3(36, Bn), 128>>>(slot);
        k_gru<<<dim3(8, Bn), 256>>>(x, gconv_w, wz_l, bz_l, wr_l, br_l, wh_l, bh_l, t, cnt);
    }

    k_cls<<<Bn, 256>>>(cls_w, cls_b, out);
}

// round 9
// speedup vs baseline: 1.9134x; 1.1488x over previous
#include <cuda_runtime.h>
#include <math.h>

#define Bn 16
#define Nn 256
#define Tn 64
#define Wn 12
#define Hn 64
#define EDn 64
#define Sn 5
#define Cn 4
#define En 2048
#define FGn 76   // W + H
#define CAP 64
#define NBLK 144

typedef unsigned long long ull;

// ---------------- f32x2 packed-FMA helpers (sm_103a FFMA2) ----------------
__device__ __forceinline__ void fma2(ull& d, ull a, ull b) {
    asm("fma.rn.f32x2 %0, %1, %2, %0;" : "+l"(d) : "l"(a), "l"(b));
}
__device__ __forceinline__ ull splat2(float v) {
    ull r; asm("mov.b64 %0, {%1, %1};" : "=l"(r) : "f"(v)); return r;
}
__device__ __forceinline__ ull pack2(float lo, float hi) {
    ull r; asm("mov.b64 %0, {%1, %2};" : "=l"(r) : "f"(lo), "f"(hi)); return r;
}
__device__ __forceinline__ float2 unpack2(ull v) {
    float lo, hi; asm("mov.b64 {%0, %1}, %2;" : "=f"(lo), "=f"(hi) : "l"(v));
    return make_float2(lo, hi);
}
__device__ __forceinline__ float hadd2(ull v) { float2 f = unpack2(v); return f.x + f.y; }

// ---------------- device scratch ----------------
__device__ float g_dinv_stat[Nn];
__device__ int   g_nbr_cnt[Nn];
__device__ int   g_nbr_idx[Nn * CAP];
__device__ float g_nbr_w[Nn * CAP];
__device__ float g_coef[6 * Hn];
__device__ float g_XW[Bn * Nn * EDn];
__device__ float g_de1[Bn * Nn * EDn];
__device__ float g_de2[Bn * Nn * EDn];
__device__ float g_Eh[(size_t)Bn * Sn * Nn * Nn];
__device__ float g_Msum[(size_t)Bn * Nn * Nn];
__device__ float g_colsum[Bn * Nn];
__device__ float g_h[Bn * Nn * Hn];
__device__ unsigned g_count;
__device__ unsigned g_gen;

// ---------------- smem layout (floats) ----------------
#define OFF_W1   0
#define OFF_W2   4096
#define OFF_WZ   8192
#define OFF_WR   12288
#define OFF_WH   16384
#define OFF_WG   20480          // 4864
#define OFF_COEF 25344          // 384
#define OFF_BIAS 25728          // 384: [b1,b2,bz,br,bh,gconv_b]
#define OFF_H    26112          // 2048 persistent h rows
#define OFF_NBRW 28160          // 2048
#define OFF_NBRI 30208          // 2048 (int view)
#define OFF_NBRC 32256          // 32 (int view)
#define OFF_WK   32288          // 9824 work area
#define SMEM_FLOATS (OFF_WK + 9824)
#define SMEM_BYTES (SMEM_FLOATS * 4)

// ---------------- grid barrier ----------------
__device__ __forceinline__ void gsync(unsigned& lgen) {
    __syncthreads();
    if (threadIdx.x == 0) {
        __threadfence();
        if (atomicAdd(&g_count, 1u) == (unsigned)(NBLK - 1)) {
            g_count = 0u;
            __threadfence();
            atomicAdd(&g_gen, 1u);
        } else {
            while (atomicAdd(&g_gen, 0u) <= lgen) { __nanosleep(32); }
        }
        __threadfence();
    }
    lgen++;
    __syncthreads();
}

// ---------------- setup kernels ----------------
__global__ void k_zero() {
    size_t idx = (size_t)blockIdx.x * blockDim.x + threadIdx.x;
    size_t str = (size_t)gridDim.x * blockDim.x;
    if (idx == 0) { g_count = 0u; g_gen = 0u; }
    for (size_t i = idx; i < (size_t)Bn * Sn * Nn * Nn; i += str) g_Eh[i] = 0.f;
    for (size_t i = idx; i < (size_t)Bn * Nn * Nn; i += str) g_Msum[i] = 0.f;
    for (size_t i = idx; i < (size_t)Bn * Nn; i += str) g_colsum[i] = 0.f;
}

__global__ void k_build(const int* __restrict__ ei, const float* __restrict__ ew) {
    int j = threadIdx.x;  // 256 threads, 1 block
    float deg = 1.0f;
    for (int e = 0; e < En; e++)
        if (ei[En + e] == j) deg += ew[e];
    g_dinv_stat[j] = 1.0f / sqrtf(deg);
    __syncthreads();
    float dj = g_dinv_stat[j];
    int cnt = 1;
    g_nbr_idx[j * CAP] = j;
    g_nbr_w[j * CAP] = dj * dj;
    for (int e = 0; e < En; e++) {
        if (ei[En + e] == j && cnt < CAP) {
            int s = ei[e];
            g_nbr_idx[j * CAP + cnt] = s;
            g_nbr_w[j * CAP + cnt] = g_dinv_stat[s] * ew[e] * dj;
            cnt++;
        }
    }
    g_nbr_cnt[j] = cnt;
}

__global__ void k_precoef(const float* wz_c, const float* wz_l, const float* bz_c,
                          const float* wr_c, const float* wr_l, const float* br_c,
                          const float* wh_c, const float* wh_l, const float* bh_c) {
    int k = threadIdx.x;  // 64 threads
    float az = 0, cz = 0, ar = 0, cr = 0, ah = 0, ch = 0;
    for (int f = 0; f < Hn; f++) {
        float wzl = wz_l[f * Hn + k], wrl = wr_l[f * Hn + k], whl = wh_l[f * Hn + k];
        az += wz_c[f] * wzl;  cz += bz_c[f] * wzl;
        ar += wr_c[f] * wrl;  cr += br_c[f] * wrl;
        ah += wh_c[f] * whl;  ch += bh_c[f] * whl;
    }
    g_coef[k] = az;        g_coef[64 + k] = cz;
    g_coef[128 + k] = ar;  g_coef[192 + k] = cr;
    g_coef[256 + k] = ah;  g_coef[320 + k] = ch;
}

// ---------------- persistent kernel: whole T-step scan ----------------
__global__ __launch_bounds__(256, 1) void k_persist(
    const float* __restrict__ x, const float* __restrict__ Wg,
    const float* __restrict__ gconv_b,
    const float* __restrict__ w1, const float* __restrict__ b1,
    const float* __restrict__ w2, const float* __restrict__ b2,
    const float* __restrict__ bz_lf, const float* __restrict__ wz_l,
    const float* __restrict__ br_lf, const float* __restrict__ wr_l,
    const float* __restrict__ bh_lf, const float* __restrict__ wh_l)
{
    extern __shared__ float sm[];
    int tid = threadIdx.x, bid = blockIdx.x;
    unsigned lgen = 0;

    float* sW1 = sm + OFF_W1;
    float* sW2 = sm + OFF_W2;
    float* sWz = sm + OFF_WZ;
    float* sWr = sm + OFF_WR;
    float* sWh = sm + OFF_WH;
    float* sWg = sm + OFF_WG;
    float* sCoef = sm + OFF_COEF;
    float* sBias = sm + OFF_BIAS;
    float* hS = sm + OFF_H;
    float* sNbrW = sm + OFF_NBRW;
    int* sNbrI = (int*)(sm + OFF_NBRI);
    int* sNbrC = (int*)(sm + OFF_NBRC);
    float* wk = sm + OFF_WK;

    // ---- load all weights once ----
    for (int i = tid; i < 4096; i += 256) {
        sW1[i] = w1[i];
        sW2[i] = w2[i];
        int r = i >> 6, c = i & 63;
        sWz[i] = wz_l[(64 + r) * 64 + c];
        sWr[i] = wr_l[(64 + r) * 64 + c];
        sWh[i] = wh_l[(64 + r) * 64 + c];
    }
    for (int i = tid; i < FGn * 64; i += 256) sWg[i] = Wg[i];
    for (int i = tid; i < 384; i += 256) sCoef[i] = g_coef[i];
    if (tid < 64) {
        sBias[tid] = b1[tid];        sBias[64 + tid] = b2[tid];
        sBias[128 + tid] = bz_lf[tid]; sBias[192 + tid] = br_lf[tid];
        sBias[256 + tid] = bh_lf[tid]; sBias[320 + tid] = gconv_b[tid];
    }
    for (int i = tid; i < 2048; i += 256) hS[i] = 0.f;

    int bA = bid >> 3, nT = bid & 7;   // fixed (batch, tile) for phases A & C
    if (bid < 128) {
        for (int i = tid; i < 32 * CAP; i += 256) {
            sNbrI[i] = g_nbr_idx[nT * 32 * CAP + i];
            sNbrW[i] = g_nbr_w[nT * 32 * CAP + i];
        }
        if (tid < 32) sNbrC[tid] = g_nbr_cnt[nT * 32 + tid];
    }
    __syncthreads();

    int tx = tid & 31, ty = tid >> 5;
    int f0 = tx * 2, r0 = ty * 4;

    // ---- initial XW (t=0, h=0) ----
    if (bid < 128) {
        float* sIt = wk;  // [32][12]
        for (int i = tid; i < 384; i += 256) {
            int rr = i / 12, c = i - rr * 12;
            int tt = c - (Wn - 1);
            sIt[i] = (tt >= 0) ? x[(bA * Nn + nT * 32 + rr) * Tn + tt] : 0.f;
        }
        __syncthreads();
        ull acc[4] = {0ull, 0ull, 0ull, 0ull};
#pragma unroll
        for (int c = 0; c < Wn; c++) {
            ull wv = *(const ull*)&sWg[c * 64 + f0];
#pragma unroll
            for (int jy = 0; jy < 4; jy++) fma2(acc[jy], splat2(sIt[(r0 + jy) * 12 + c]), wv);
        }
#pragma unroll
        for (int jy = 0; jy < 4; jy++)
            *(float2*)&g_XW[(bA * Nn + nT * 32 + r0 + jy) * EDn + f0] = unpack2(acc[jy]);
    }
    gsync(lgen);

    for (int t = 0; t < Tn; t++) {
        int slot = t % Sn;
        float cnt = (float)((t + 1 < Sn) ? (t + 1) : Sn);

        // ================= phase A: df gather + de1/de2 =================
        if (bid < 128) {
            float* dfS = wk;  // [32][64]
            {
                int f = tid & 63, jg = tid >> 6;
                float gb = sBias[320 + f];
#pragma unroll
                for (int q = 0; q < 8; q++) {
                    int jl = jg + q * 4;
                    int nc = sNbrC[jl];
                    float acc = 0.f;
                    for (int k = 0; k < nc; k++)
                        acc += sNbrW[jl * CAP + k] * g_XW[(bA * Nn + sNbrI[jl * CAP + k]) * EDn + f];
                    dfS[jl * 64 + f] = acc + gb;
                }
            }
            __syncthreads();
            ull a1[4], a2[4];
#pragma unroll
            for (int jy = 0; jy < 4; jy++) { a1[jy] = 0ull; a2[jy] = 0ull; }
#pragma unroll 4
            for (int ff = 0; ff < 64; ff += 4) {
                float4 D[4];
#pragma unroll
                for (int jy = 0; jy < 4; jy++) D[jy] = *(const float4*)&dfS[(r0 + jy) * 64 + ff];
                const float* Dp = (const float*)D;
#pragma unroll
                for (int s = 0; s < 4; s++) {
                    ull w1v = *(const ull*)&sW1[(ff + s) * 64 + f0];
                    ull w2v = *(const ull*)&sW2[(ff + s) * 64 + f0];
#pragma unroll
                    for (int jy = 0; jy < 4; jy++) {
                        ull dv = splat2(Dp[jy * 4 + s]);
                        fma2(a1[jy], dv, w1v);
                        fma2(a2[jy], dv, w2v);
                    }
                }
            }
            {
                float bb10 = sBias[f0], bb11 = sBias[f0 + 1];
                float bb20 = sBias[64 + f0], bb21 = sBias[64 + f0 + 1];
#pragma unroll
                for (int jy = 0; jy < 4; jy++) {
                    int row = (bA * Nn + nT * 32 + r0 + jy) * EDn;
                    float2 v1 = unpack2(a1[jy]);
                    float2 v2 = unpack2(a2[jy]);
                    *(float2*)&g_de1[row + f0] = make_float2(tanhf(v1.x + bb10), tanhf(v1.y + bb11));
                    *(float2*)&g_de2[row + f0] = make_float2(tanhf(v2.x + bb20), tanhf(v2.y + bb21));
                }
            }
        }
        gsync(lgen);

        // ================= phase B: Et tiles (4 per block) =================
        {
            float* d1i = wk;
            float* d2i = wk + 2176;
            float* d1j = wk + 4352;
            float* d2j = wk + 6528;
            float* tS  = wk + 8704;   // stride 33
            float* colbuf = wk + 9760;
            int bx = tid & 7, by = tid >> 3;   // by = ii (0..31); jj = bx + 8c
#pragma unroll 1
            for (int k4 = 0; k4 < 4; k4++) {
                int u = bid + NBLK * k4;       // < 576
                int bb = u / 36;
                int p = u - bb * 36;
                int iT = 0;
                while (p >= 8 - iT) { p -= 8 - iT; iT++; }
                int jT = iT + p;
                bool diag = (iT == jT);

                for (int i = tid; i < 512; i += 256) {
                    int rr = i >> 4, e = (i & 15) * 4;
                    int gi = (bb * Nn + iT * 32 + rr) * EDn + e;
                    int gj = (bb * Nn + jT * 32 + rr) * EDn + e;
                    *(float4*)&d1i[rr * 68 + e] = *(const float4*)&g_de1[gi];
                    *(float4*)&d2i[rr * 68 + e] = *(const float4*)&g_de2[gi];
                    *(float4*)&d1j[rr * 68 + e] = *(const float4*)&g_de1[gj];
                    *(float4*)&d2j[rr * 68 + e] = *(const float4*)&g_de2[gj];
                }
                if (tid < 64) colbuf[tid] = 0.f;
                __syncthreads();

                ull accA[4], accB[4];
#pragma unroll
                for (int c = 0; c < 4; c++) { accA[c] = 0ull; accB[c] = 0ull; }
#pragma unroll
                for (int e0 = 0; e0 < 64; e0 += 4) {
                    ulonglong2 P1 = *(const ulonglong2*)&d1i[by * 68 + e0];
                    ulonglong2 P2 = *(const ulonglong2*)&d2i[by * 68 + e0];
#pragma unroll
                    for (int c = 0; c < 4; c++) {
                        ulonglong2 Q1 = *(const ulonglong2*)&d1j[(bx + 8 * c) * 68 + e0];
                        ulonglong2 Q2 = *(const ulonglong2*)&d2j[(bx + 8 * c) * 68 + e0];
                        fma2(accA[c], P1.x, Q2.x);  fma2(accA[c], P1.y, Q2.y);
                        fma2(accB[c], Q1.x, P2.x);  fma2(accB[c], Q1.y, P2.y);
                    }
                }
                float tv[4];
#pragma unroll
                for (int c = 0; c < 4; c++) {
                    tv[c] = tanhf(hadd2(accA[c]) - hadd2(accB[c]));
                    tS[by * 33 + bx + 8 * c] = tv[c];
                }
                __syncthreads();

                size_t ebase = ((size_t)(bb * Sn + slot) * Nn) * Nn;
                size_t mbase = ((size_t)bb * Nn) * Nn;
#pragma unroll
                for (int q = 0; q < 4; q++) {
                    int idx = tid + q * 256;
                    int ii = idx >> 5, jj = idx & 31;
                    float et = fmaxf(tS[ii * 33 + jj], 0.f);
                    size_t eo = ebase + (size_t)(iT * 32 + ii) * Nn + jT * 32 + jj;
                    float old = g_Eh[eo];
                    g_Eh[eo] = et;
                    float d = et - old;
                    g_Msum[mbase + (size_t)(iT * 32 + ii) * Nn + jT * 32 + jj] += d;
                    atomicAdd(&colbuf[jj], d);
                }
                if (!diag) {
                    __syncthreads();
#pragma unroll
                    for (int c = 0; c < 4; c++)
                        tS[(bx + 8 * c) * 33 + by] = fmaxf(-tv[c], 0.f);
                    __syncthreads();
#pragma unroll
                    for (int q = 0; q < 4; q++) {
                        int idx = tid + q * 256;
                        int rr = idx >> 5, cc = idx & 31;
                        float et = tS[rr * 33 + cc];
                        size_t eo = ebase + (size_t)(jT * 32 + rr) * Nn + iT * 32 + cc;
                        float old = g_Eh[eo];
                        g_Eh[eo] = et;
                        float d = et - old;
                        g_Msum[mbase + (size_t)(jT * 32 + rr) * Nn + iT * 32 + cc] += d;
                        atomicAdd(&colbuf[32 + cc], d);
                    }
                }
                __syncthreads();
                if (tid < 32) atomicAdd(&g_colsum[bb * Nn + jT * 32 + tid], colbuf[tid]);
                if (!diag && tid >= 32 && tid < 64)
                    atomicAdd(&g_colsum[bb * Nn + iT * 32 + (tid - 32)], colbuf[tid]);
                __syncthreads();
            }
        }
        gsync(lgen);

        // ================= phase C: s-reduction + GRU + next XW =================
        if (bid < 128) {
            int n0 = nT * 32;
            float* hrS   = wk;          // [32][64]
            float* dinvS = wk + 2048;   // 256
            float* dxvS  = wk + 2304;   // 256
            float* part  = wk + 2560;   // 256
            float* sS    = wk + 2816;   // 32
            float* sIt   = wk + 2848;   // [32][12]
            float inv_cnt = 1.0f / cnt;

            {
                int i = tid;
                float cs = g_colsum[bA * Nn + i];
                float dv = 1.0f / sqrtf(cs * inv_cnt + 1.0f);
                dinvS[i] = dv;
                dxvS[i] = dv * x[(bA * Nn + i) * Tn + t];
            }
            if (t < Tn - 1) {
                for (int i = tid; i < 384; i += 256) {
                    int rr = i / 12, c = i - rr * 12;
                    int tt = t + 1 + c - (Wn - 1);
                    sIt[i] = (tt >= 0) ? x[(bA * Nn + n0 + rr) * Tn + tt] : 0.f;
                }
            }
            __syncthreads();
            {
                int c = tid & 31, g = tid >> 5;
                float acc = 0.f;
                int ibase = g * 32;
#pragma unroll 8
                for (int k = 0; k < 32; k++) {
                    int i = ibase + k;
                    acc += g_Msum[((size_t)bA * Nn + i) * Nn + n0 + c] * dxvS[i];
                }
                part[g * 32 + c] = acc;
            }
            __syncthreads();
            if (tid < 32) {
                float sraw = 0.f;
#pragma unroll
                for (int g = 0; g < 8; g++) sraw += part[g * 32 + tid];
                int n = n0 + tid;
                float dj = dinvS[n];
                sS[tid] = dj * (sraw * inv_cnt + dj * x[(bA * Nn + n) * Tn + t]);
            }
            __syncthreads();

            float2 zz[4];
            // ---- z gate ----
            {
                float c0 = sCoef[f0], c1 = sCoef[f0 + 1];
                float d0 = sCoef[64 + f0], d1 = sCoef[64 + f0 + 1];
                float bz0 = sBias[128 + f0], bz1 = sBias[128 + f0 + 1];
                ull acc[4];
#pragma unroll
                for (int jy = 0; jy < 4; jy++) {
                    float s = sS[r0 + jy];
                    acc[jy] = pack2(s * c0 + d0 + bz0, s * c1 + d1 + bz1);
                }
#pragma unroll 4
                for (int ff = 0; ff < 64; ff += 4) {
                    float4 Hq[4];
#pragma unroll
                    for (int jy = 0; jy < 4; jy++) Hq[jy] = *(const float4*)&hS[(r0 + jy) * 64 + ff];
                    const float* Hp = (const float*)Hq;
#pragma unroll
                    for (int s = 0; s < 4; s++) {
                        ull wv = *(const ull*)&sWz[(ff + s) * 64 + f0];
#pragma unroll
                        for (int jy = 0; jy < 4; jy++) fma2(acc[jy], splat2(Hp[jy * 4 + s]), wv);
                    }
                }
#pragma unroll
                for (int jy = 0; jy < 4; jy++) {
                    float2 a = unpack2(acc[jy]);
                    zz[jy] = make_float2(1.0f / (1.0f + expf(-a.x)), 1.0f / (1.0f + expf(-a.y)));
                }
            }
            // ---- r gate -> hrS ----
            {
                float c0 = sCoef[128 + f0], c1 = sCoef[128 + f0 + 1];
                float d0 = sCoef[192 + f0], d1 = sCoef[192 + f0 + 1];
                float br0 = sBias[192 + f0], br1 = sBias[192 + f0 + 1];
                ull acc[4];
#pragma unroll
                for (int jy = 0; jy < 4; jy++) {
                    float s = sS[r0 + jy];
                    acc[jy] = pack2(s * c0 + d0 + br0, s * c1 + d1 + br1);
                }
#pragma unroll 4
                for (int ff = 0; ff < 64; ff += 4) {
                    float4 Hq[4];
#pragma unroll
                    for (int jy = 0; jy < 4; jy++) Hq[jy] = *(const float4*)&hS[(r0 + jy) * 64 + ff];
                    const float* Hp = (const float*)Hq;
#pragma unroll
                    for (int s = 0; s < 4; s++) {
                        ull wv = *(const ull*)&sWr[(ff + s) * 64 + f0];
#pragma unroll
                        for (int jy = 0; jy < 4; jy++) fma2(acc[jy], splat2(Hp[jy * 4 + s]), wv);
                    }
                }
#pragma unroll
                for (int jy = 0; jy < 4; jy++) {
                    float2 a = unpack2(acc[jy]);
                    float rv0 = 1.0f / (1.0f + expf(-a.x));
                    float rv1 = 1.0f / (1.0f + expf(-a.y));
                    float2 hv = *(const float2*)&hS[(r0 + jy) * 64 + f0];
                    *(float2*)&hrS[(r0 + jy) * 64 + f0] = make_float2(hv.x * rv0, hv.y * rv1);
                }
            }
            __syncwarp();
            // ---- h candidate + combine (hS updated in place; rows are warp-private) ----
            {
                float c0 = sCoef[256 + f0], c1 = sCoef[256 + f0 + 1];
                float d0 = sCoef[320 + f0], d1 = sCoef[320 + f0 + 1];
                float bh0 = sBias[256 + f0], bh1 = sBias[256 + f0 + 1];
                ull acc[4];
#pragma unroll
                for (int jy = 0; jy < 4; jy++) {
                    float s = sS[r0 + jy];
                    acc[jy] = pack2(s * c0 + d0 + bh0, s * c1 + d1 + bh1);
                }
#pragma unroll 4
                for (int ff = 0; ff < 64; ff += 4) {
                    float4 Hq[4];
#pragma unroll
                    for (int jy = 0; jy < 4; jy++) Hq[jy] = *(const float4*)&hrS[(r0 + jy) * 64 + ff];
                    const float* Hp = (const float*)Hq;
#pragma unroll
                    for (int s = 0; s < 4; s++) {
                        ull wv = *(const ull*)&sWh[(ff + s) * 64 + f0];
#pragma unroll
                        for (int jy = 0; jy < 4; jy++) fma2(acc[jy], splat2(Hp[jy * 4 + s]), wv);
                    }
                }
                __syncwarp();
#pragma unroll
                for (int jy = 0; jy < 4; jy++) {
                    float2 a = unpack2(acc[jy]);
                    float ht0 = tanhf(a.x);
                    float ht1 = tanhf(a.y);
                    float2 hv = *(const float2*)&hS[(r0 + jy) * 64 + f0];
                    float hn0 = zz[jy].x * hv.x + (1.0f - zz[jy].x) * ht0;
                    float hn1 = zz[jy].y * hv.y + (1.0f - zz[jy].y) * ht1;
                    *(float2*)&hS[(r0 + jy) * 64 + f0] = make_float2(hn0, hn1);
                    if (t == Tn - 1)
                        *(float2*)&g_h[(bA * Nn + n0 + r0 + jy) * Hn + f0] = make_float2(hn0, hn1);
                }
            }
            // ---- next-step XW ----
            if (t < Tn - 1) {
                __syncthreads();   // sIt ready (cross-warp); hS updates are warp-local
                ull acc[4] = {0ull, 0ull, 0ull, 0ull};
#pragma unroll
                for (int c = 0; c < Wn; c++) {
                    ull wv = *(const ull*)&sWg[c * 64 + f0];
#pragma unroll
                    for (int jy = 0; jy < 4; jy++) fma2(acc[jy], splat2(sIt[(r0 + jy) * 12 + c]), wv);
                }
#pragma unroll 4
                for (int c = 0; c < Hn; c++) {
                    ull wv = *(const ull*)&sWg[(Wn + c) * 64 + f0];
#pragma unroll
                    for (int jy = 0; jy < 4; jy++) fma2(acc[jy], splat2(hS[(r0 + jy) * 64 + c]), wv);
                }
#pragma unroll
                for (int jy = 0; jy < 4; jy++)
                    *(float2*)&g_XW[(bA * Nn + n0 + r0 + jy) * EDn + f0] = unpack2(acc[jy]);
            }
        }
        gsync(lgen);
    }
}

// ---------------- final classifier ----------------
__global__ __launch_bounds__(256) void k_cls(const float* __restrict__ cls_w,
                                             const float* __restrict__ cls_b,
                                             float* __restrict__ out) {
    int b = blockIdx.x, tid = threadIdx.x;
    float acc[4] = {0.f, 0.f, 0.f, 0.f};
    for (int i = tid; i < Nn * Hn; i += 256) {
        float hv = g_h[b * Nn * Hn + i];
#pragma unroll
        for (int c = 0; c < 4; c++) acc[c] += hv * cls_w[i * Cn + c];
    }
    __shared__ float red[4][256];
#pragma unroll
    for (int c = 0; c < 4; c++) red[c][tid] = acc[c];
    __syncthreads();
    for (int s = 128; s > 0; s >>= 1) {
        if (tid < s) {
#pragma unroll
            for (int c = 0; c < 4; c++) red[c][tid] += red[c][tid + s];
        }
        __syncthreads();
    }
    if (tid < 4) out[b * Cn + tid] = red[tid][0] + cls_b[tid];
}

// ---------------- launch ----------------
extern "C" void kernel_launch(void* const* d_in, const int* in_sizes, int n_in,
                              void* d_out, int out_size) {
    const float* x        = (const float*)d_in[0];
    const float* ew       = (const float*)d_in[1];
    const float* gconv_w  = (const float*)d_in[2];
    const float* gconv_b  = (const float*)d_in[3];
    const float* w1       = (const float*)d_in[4];
    const float* b1       = (const float*)d_in[5];
    const float* w2       = (const float*)d_in[6];
    const float* b2       = (const float*)d_in[7];
    const float* wz_c     = (const float*)d_in[8];
    const float* bz_c     = (const float*)d_in[9];
    const float* wz_l     = (const float*)d_in[10];
    const float* bz_l     = (const float*)d_in[11];
    const float* wr_c     = (const float*)d_in[12];
    const float* br_c     = (const float*)d_in[13];
    const float* wr_l     = (const float*)d_in[14];
    const float* br_l     = (const float*)d_in[15];
    const float* wh_c     = (const float*)d_in[16];
    const float* bh_c     = (const float*)d_in[17];
    const float* wh_l     = (const float*)d_in[18];
    const float* bh_l     = (const float*)d_in[19];
    const float* cls_w    = (const float*)d_in[20];
    const float* cls_b    = (const float*)d_in[21];
    const int*   eidx     = (const int*)d_in[22];
    float* out = (float*)d_out;

    static int smem_set = 0;
    if (!smem_set) {
        cudaFuncSetAttribute(k_persist, cudaFuncAttributeMaxDynamicSharedMemorySize, SMEM_BYTES);
        smem_set = 1;
    }

    k_zero<<<2048, 256>>>();
    k_build<<<1, 256>>>(eidx, ew);
    k_precoef<<<1, 64>>>(wz_c, wz_l, bz_c, wr_c, wr_l, br_c, wh_c, wh_l, bh_c);
    k_persist<<<NBLK, 256, SMEM_BYTES>>>(x, gconv_w, gconv_b, w1, b1, w2, b2,
                                         bz_l, wz_l, br_l, wr_l, bh_l, wh_l);
    k_cls<<<Bn, 256>>>(cls_w, cls_b, out);
}

// round 10
// speedup vs baseline: 1.9585x; 1.0236x over previous
#include <cuda_runtime.h>
#include <math.h>

#define Bn 16
#define Nn 256
#define Tn 64
#define Wn 12
#define Hn 64
#define EDn 64
#define Sn 5
#define Cn 4
#define En 2048
#define FGn 76   // W + H
#define CAP 64
#define GBLK 9            // blocks per batch group
#define NBLK (Bn * GBLK)  // 144

typedef unsigned long long ull;

// ---------------- f32x2 packed-FMA helpers (sm_103a FFMA2) ----------------
__device__ __forceinline__ void fma2(ull& d, ull a, ull b) {
    asm("fma.rn.f32x2 %0, %1, %2, %0;" : "+l"(d) : "l"(a), "l"(b));
}
__device__ __forceinline__ ull splat2(float v) {
    ull r; asm("mov.b64 %0, {%1, %1};" : "=l"(r) : "f"(v)); return r;
}
__device__ __forceinline__ ull pack2(float lo, float hi) {
    ull r; asm("mov.b64 %0, {%1, %2};" : "=l"(r) : "f"(lo), "f"(hi)); return r;
}
__device__ __forceinline__ float2 unpack2(ull v) {
    float lo, hi; asm("mov.b64 {%0, %1}, %2;" : "=f"(lo), "=f"(hi) : "l"(v));
    return make_float2(lo, hi);
}
__device__ __forceinline__ float hadd2(ull v) { float2 f = unpack2(v); return f.x + f.y; }

// triangular pair LUT (36 pairs of 8x8 tiles)
__device__ __constant__ signed char c_iT[36] =
    {0,0,0,0,0,0,0,0, 1,1,1,1,1,1,1, 2,2,2,2,2,2, 3,3,3,3,3, 4,4,4,4, 5,5,5, 6,6, 7};
__device__ __constant__ signed char c_jT[36] =
    {0,1,2,3,4,5,6,7, 1,2,3,4,5,6,7, 2,3,4,5,6,7, 3,4,5,6,7, 4,5,6,7, 5,6,7, 6,7, 7};

// ---------------- device scratch ----------------
__device__ float g_dinv_stat[Nn];
__device__ int   g_nbr_cnt[Nn];
__device__ int   g_nbr_idx[Nn * CAP];
__device__ float g_nbr_w[Nn * CAP];
__device__ float g_coef[6 * Hn];
__device__ float g_XW[Bn * Nn * EDn];
__device__ float g_de1[Bn * Nn * EDn];
__device__ float g_de2[Bn * Nn * EDn];
__device__ float g_Eh[(size_t)Bn * Sn * Nn * Nn];
__device__ float g_Msum[(size_t)Bn * Nn * Nn];
__device__ float g_colsum[Bn * Nn];
__device__ float g_h[Bn * Nn * Hn];
__device__ unsigned g_bcount[Bn * 32];   // one counter per batch, 128B apart
__device__ unsigned g_bgen[Bn * 32];

// ---------------- smem layout (floats) ----------------
#define OFF_W1   0
#define OFF_W2   4096
#define OFF_WZ   8192
#define OFF_WR   12288
#define OFF_WH   16384
#define OFF_WG   20480          // 4864
#define OFF_COEF 25344          // 384
#define OFF_BIAS 25728          // 384: [b1,b2,bz,br,bh,gconv_b]
#define OFF_H    26112          // 2048 persistent h rows
#define OFF_NBRW 28160          // 2048
#define OFF_NBRI 30208          // 2048 (int view)
#define OFF_NBRC 32256          // 32 (int view)
#define OFF_WK   32288          // 9824 work area
#define SMEM_FLOATS (OFF_WK + 9824)
#define SMEM_BYTES (SMEM_FLOATS * 4)

// ---------------- per-batch grid barrier (9 arrivals) ----------------
__device__ __forceinline__ void gsync_b(int grp, unsigned& lgen) {
    __syncthreads();
    if (threadIdx.x == 0) {
        unsigned* cnt = &g_bcount[grp * 32];
        unsigned* gen = &g_bgen[grp * 32];
        __threadfence();
        if (atomicAdd(cnt, 1u) == (unsigned)(GBLK - 1)) {
            *cnt = 0u;
            __threadfence();
            atomicAdd(gen, 1u);
        } else {
            while (atomicAdd(gen, 0u) <= lgen) { __nanosleep(20); }
        }
        __threadfence();
    }
    lgen++;
    __syncthreads();
}

// ---------------- setup kernels ----------------
__global__ void k_zero() {
    size_t idx = (size_t)blockIdx.x * blockDim.x + threadIdx.x;
    size_t str = (size_t)gridDim.x * blockDim.x;
    if (idx < Bn * 32) { g_bcount[idx] = 0u; g_bgen[idx] = 0u; }
    for (size_t i = idx; i < (size_t)Bn * Sn * Nn * Nn; i += str) g_Eh[i] = 0.f;
    for (size_t i = idx; i < (size_t)Bn * Nn * Nn; i += str) g_Msum[i] = 0.f;
    for (size_t i = idx; i < (size_t)Bn * Nn; i += str) g_colsum[i] = 0.f;
}

__global__ void k_build(const int* __restrict__ ei, const float* __restrict__ ew) {
    int j = threadIdx.x;  // 256 threads, 1 block
    float deg = 1.0f;
    for (int e = 0; e < En; e++)
        if (ei[En + e] == j) deg += ew[e];
    g_dinv_stat[j] = 1.0f / sqrtf(deg);
    __syncthreads();
    float dj = g_dinv_stat[j];
    int cnt = 1;
    g_nbr_idx[j * CAP] = j;
    g_nbr_w[j * CAP] = dj * dj;
    for (int e = 0; e < En; e++) {
        if (ei[En + e] == j && cnt < CAP) {
            int s = ei[e];
            g_nbr_idx[j * CAP + cnt] = s;
            g_nbr_w[j * CAP + cnt] = g_dinv_stat[s] * ew[e] * dj;
            cnt++;
        }
    }
    g_nbr_cnt[j] = cnt;
}

__global__ void k_precoef(const float* wz_c, const float* wz_l, const float* bz_c,
                          const float* wr_c, const float* wr_l, const float* br_c,
                          const float* wh_c, const float* wh_l, const float* bh_c) {
    int k = threadIdx.x;  // 64 threads
    float az = 0, cz = 0, ar = 0, cr = 0, ah = 0, ch = 0;
    for (int f = 0; f < Hn; f++) {
        float wzl = wz_l[f * Hn + k], wrl = wr_l[f * Hn + k], whl = wh_l[f * Hn + k];
        az += wz_c[f] * wzl;  cz += bz_c[f] * wzl;
        ar += wr_c[f] * wrl;  cr += br_c[f] * wrl;
        ah += wh_c[f] * whl;  ch += bh_c[f] * whl;
    }
    g_coef[k] = az;        g_coef[64 + k] = cz;
    g_coef[128 + k] = ar;  g_coef[192 + k] = cr;
    g_coef[256 + k] = ah;  g_coef[320 + k] = ch;
}

// ---------------- persistent kernel: whole T-step scan ----------------
__global__ __launch_bounds__(256, 1) void k_persist(
    const float* __restrict__ x, const float* __restrict__ Wg,
    const float* __restrict__ gconv_b,
    const float* __restrict__ w1, const float* __restrict__ b1,
    const float* __restrict__ w2, const float* __restrict__ b2,
    const float* __restrict__ bz_lf, const float* __restrict__ wz_l,
    const float* __restrict__ br_lf, const float* __restrict__ wr_l,
    const float* __restrict__ bh_lf, const float* __restrict__ wh_l)
{
    extern __shared__ float sm[];
    int tid = threadIdx.x, bid = blockIdx.x;
    int grp = bid / GBLK;          // batch
    int role = bid - grp * GBLK;   // 0..8
    int bA = grp, nT = role;       // phases A/C active when role < 8
    bool ac_on = (role < 8);
    unsigned lgen = 0;

    float* sW1 = sm + OFF_W1;
    float* sW2 = sm + OFF_W2;
    float* sWz = sm + OFF_WZ;
    float* sWr = sm + OFF_WR;
    float* sWh = sm + OFF_WH;
    float* sWg = sm + OFF_WG;
    float* sCoef = sm + OFF_COEF;
    float* sBias = sm + OFF_BIAS;
    float* hS = sm + OFF_H;
    float* sNbrW = sm + OFF_NBRW;
    int* sNbrI = (int*)(sm + OFF_NBRI);
    int* sNbrC = (int*)(sm + OFF_NBRC);
    float* wk = sm + OFF_WK;

    // ---- load all weights once ----
    for (int i = tid; i < 4096; i += 256) {
        sW1[i] = w1[i];
        sW2[i] = w2[i];
        int r = i >> 6, c = i & 63;
        sWz[i] = wz_l[(64 + r) * 64 + c];
        sWr[i] = wr_l[(64 + r) * 64 + c];
        sWh[i] = wh_l[(64 + r) * 64 + c];
    }
    for (int i = tid; i < FGn * 64; i += 256) sWg[i] = Wg[i];
    for (int i = tid; i < 384; i += 256) sCoef[i] = g_coef[i];
    if (tid < 64) {
        sBias[tid] = b1[tid];        sBias[64 + tid] = b2[tid];
        sBias[128 + tid] = bz_lf[tid]; sBias[192 + tid] = br_lf[tid];
        sBias[256 + tid] = bh_lf[tid]; sBias[320 + tid] = gconv_b[tid];
    }
    for (int i = tid; i < 2048; i += 256) hS[i] = 0.f;

    if (ac_on) {
        for (int i = tid; i < 32 * CAP; i += 256) {
            sNbrI[i] = g_nbr_idx[nT * 32 * CAP + i];
            sNbrW[i] = g_nbr_w[nT * 32 * CAP + i];
        }
        if (tid < 32) sNbrC[tid] = g_nbr_cnt[nT * 32 + tid];
    }
    __syncthreads();

    int tx = tid & 31, ty = tid >> 5;
    int f0 = tx * 2, r0 = ty * 4;

    // ---- initial XW (t=0, h=0) ----
    if (ac_on) {
        float* sIt = wk;  // [32][12]
        for (int i = tid; i < 384; i += 256) {
            int rr = i / 12, c = i - rr * 12;
            int tt = c - (Wn - 1);
            sIt[i] = (tt >= 0) ? x[(bA * Nn + nT * 32 + rr) * Tn + tt] : 0.f;
        }
        __syncthreads();
        ull acc[4] = {0ull, 0ull, 0ull, 0ull};
#pragma unroll
        for (int c = 0; c < Wn; c++) {
            ull wv = *(const ull*)&sWg[c * 64 + f0];
#pragma unroll
            for (int jy = 0; jy < 4; jy++) fma2(acc[jy], splat2(sIt[(r0 + jy) * 12 + c]), wv);
        }
#pragma unroll
        for (int jy = 0; jy < 4; jy++)
            *(float2*)&g_XW[(bA * Nn + nT * 32 + r0 + jy) * EDn + f0] = unpack2(acc[jy]);
    }
    gsync_b(grp, lgen);

    for (int t = 0; t < Tn; t++) {
        int slot = t % Sn;
        float cnt = (float)((t + 1 < Sn) ? (t + 1) : Sn);

        // ================= phase A: df gather + de1/de2 =================
        if (ac_on) {
            float* dfS = wk;  // [32][64]
            {
                int f = tid & 63, jg = tid >> 6;
                float gb = sBias[320 + f];
#pragma unroll
                for (int q = 0; q < 8; q++) {
                    int jl = jg + q * 4;
                    int nc = sNbrC[jl];
                    float acc = 0.f;
                    for (int k = 0; k < nc; k++)
                        acc += sNbrW[jl * CAP + k] * g_XW[(bA * Nn + sNbrI[jl * CAP + k]) * EDn + f];
                    dfS[jl * 64 + f] = acc + gb;
                }
            }
            __syncthreads();
            ull a1[4], a2[4];
#pragma unroll
            for (int jy = 0; jy < 4; jy++) { a1[jy] = 0ull; a2[jy] = 0ull; }
#pragma unroll 4
            for (int ff = 0; ff < 64; ff += 4) {
                float4 D[4];
#pragma unroll
                for (int jy = 0; jy < 4; jy++) D[jy] = *(const float4*)&dfS[(r0 + jy) * 64 + ff];
                const float* Dp = (const float*)D;
#pragma unroll
                for (int s = 0; s < 4; s++) {
                    ull w1v = *(const ull*)&sW1[(ff + s) * 64 + f0];
                    ull w2v = *(const ull*)&sW2[(ff + s) * 64 + f0];
#pragma unroll
                    for (int jy = 0; jy < 4; jy++) {
                        ull dv = splat2(Dp[jy * 4 + s]);
                        fma2(a1[jy], dv, w1v);
                        fma2(a2[jy], dv, w2v);
                    }
                }
            }
            {
                float bb10 = sBias[f0], bb11 = sBias[f0 + 1];
                float bb20 = sBias[64 + f0], bb21 = sBias[64 + f0 + 1];
#pragma unroll
                for (int jy = 0; jy < 4; jy++) {
                    int row = (bA * Nn + nT * 32 + r0 + jy) * EDn;
                    float2 v1 = unpack2(a1[jy]);
                    float2 v2 = unpack2(a2[jy]);
                    *(float2*)&g_de1[row + f0] = make_float2(tanhf(v1.x + bb10), tanhf(v1.y + bb11));
                    *(float2*)&g_de2[row + f0] = make_float2(tanhf(v2.x + bb20), tanhf(v2.y + bb21));
                }
            }
        }
        gsync_b(grp, lgen);

        // ================= phase B: Et tiles (4 per block, own batch) =================
        {
            float* d1i = wk;
            float* d2i = wk + 2176;
            float* d1j = wk + 4352;
            float* d2j = wk + 6528;
            float* tS  = wk + 8704;   // stride 33
            float* colbuf = wk + 9760;
            int bx = tid & 7, by = tid >> 3;
#pragma unroll 1
            for (int k4 = 0; k4 < 4; k4++) {
                int u = role * 4 + k4;
                if (u >= 36) break;
                int iT = c_iT[u], jT = c_jT[u];
                bool diag = (iT == jT);
                int bb = bA;

                for (int i = tid; i < 512; i += 256) {
                    int rr = i >> 4, e = (i & 15) * 4;
                    int gi = (bb * Nn + iT * 32 + rr) * EDn + e;
                    int gj = (bb * Nn + jT * 32 + rr) * EDn + e;
                    *(float4*)&d1i[rr * 68 + e] = *(const float4*)&g_de1[gi];
                    *(float4*)&d2i[rr * 68 + e] = *(const float4*)&g_de2[gi];
                    *(float4*)&d1j[rr * 68 + e] = *(const float4*)&g_de1[gj];
                    *(float4*)&d2j[rr * 68 + e] = *(const float4*)&g_de2[gj];
                }
                if (tid < 64) colbuf[tid] = 0.f;
                __syncthreads();

                ull accA[4], accB[4];
#pragma unroll
                for (int c = 0; c < 4; c++) { accA[c] = 0ull; accB[c] = 0ull; }
#pragma unroll
                for (int e0 = 0; e0 < 64; e0 += 4) {
                    ulonglong2 P1 = *(const ulonglong2*)&d1i[by * 68 + e0];
                    ulonglong2 P2 = *(const ulonglong2*)&d2i[by * 68 + e0];
#pragma unroll
                    for (int c = 0; c < 4; c++) {
                        ulonglong2 Q1 = *(const ulonglong2*)&d1j[(bx + 8 * c) * 68 + e0];
                        ulonglong2 Q2 = *(const ulonglong2*)&d2j[(bx + 8 * c) * 68 + e0];
                        fma2(accA[c], P1.x, Q2.x);  fma2(accA[c], P1.y, Q2.y);
                        fma2(accB[c], Q1.x, P2.x);  fma2(accB[c], Q1.y, P2.y);
                    }
                }
                float tv[4];
#pragma unroll
                for (int c = 0; c < 4; c++) {
                    tv[c] = tanhf(hadd2(accA[c]) - hadd2(accB[c]));
                    tS[by * 33 + bx + 8 * c] = tv[c];
                }
                __syncthreads();

                size_t ebase = ((size_t)(bb * Sn + slot) * Nn) * Nn;
                size_t mbase = ((size_t)bb * Nn) * Nn;
#pragma unroll
                for (int q = 0; q < 4; q++) {
                    int idx = tid + q * 256;
                    int ii = idx >> 5, jj = idx & 31;
                    float et = fmaxf(tS[ii * 33 + jj], 0.f);
                    size_t eo = ebase + (size_t)(iT * 32 + ii) * Nn + jT * 32 + jj;
                    float old = g_Eh[eo];
                    g_Eh[eo] = et;
                    float d = et - old;
                    g_Msum[mbase + (size_t)(iT * 32 + ii) * Nn + jT * 32 + jj] += d;
                    atomicAdd(&colbuf[jj], d);
                }
                if (!diag) {
                    __syncthreads();
#pragma unroll
                    for (int c = 0; c < 4; c++)
                        tS[(bx + 8 * c) * 33 + by] = fmaxf(-tv[c], 0.f);
                    __syncthreads();
#pragma unroll
                    for (int q = 0; q < 4; q++) {
                        int idx = tid + q * 256;
                        int rr = idx >> 5, cc = idx & 31;
                        float et = tS[rr * 33 + cc];
                        size_t eo = ebase + (size_t)(jT * 32 + rr) * Nn + iT * 32 + cc;
                        float old = g_Eh[eo];
                        g_Eh[eo] = et;
                        float d = et - old;
                        g_Msum[mbase + (size_t)(jT * 32 + rr) * Nn + iT * 32 + cc] += d;
                        atomicAdd(&colbuf[32 + cc], d);
                    }
                }
                __syncthreads();
                if (tid < 32) atomicAdd(&g_colsum[bb * Nn + jT * 32 + tid], colbuf[tid]);
                if (!diag && tid >= 32 && tid < 64)
                    atomicAdd(&g_colsum[bb * Nn + iT * 32 + (tid - 32)], colbuf[tid]);
                __syncthreads();
            }
        }
        gsync_b(grp, lgen);

        // ================= phase C: s-reduction + GRU + next XW =================
        if (ac_on) {
            int n0 = nT * 32;
            float* hrS   = wk;          // [32][64]
            float* dinvS = wk + 2048;   // 256
            float* dxvS  = wk + 2304;   // 256
            float* part  = wk + 2560;   // 256
            float* sS    = wk + 2816;   // 32
            float* sIt   = wk + 2848;   // [32][12]
            float inv_cnt = 1.0f / cnt;

            {
                int i = tid;
                float cs = g_colsum[bA * Nn + i];
                float dv = 1.0f / sqrtf(cs * inv_cnt + 1.0f);
                dinvS[i] = dv;
                dxvS[i] = dv * x[(bA * Nn + i) * Tn + t];
            }
            if (t < Tn - 1) {
                for (int i = tid; i < 384; i += 256) {
                    int rr = i / 12, c = i - rr * 12;
                    int tt = t + 1 + c - (Wn - 1);
                    sIt[i] = (tt >= 0) ? x[(bA * Nn + n0 + rr) * Tn + tt] : 0.f;
                }
            }
            __syncthreads();
            {
                int c = tid & 31, g = tid >> 5;
                float acc = 0.f;
                int ibase = g * 32;
#pragma unroll 8
                for (int k = 0; k < 32; k++) {
                    int i = ibase + k;
                    acc += g_Msum[((size_t)bA * Nn + i) * Nn + n0 + c] * dxvS[i];
                }
                part[g * 32 + c] = acc;
            }
            __syncthreads();
            if (tid < 32) {
                float sraw = 0.f;
#pragma unroll
                for (int g = 0; g < 8; g++) sraw += part[g * 32 + tid];
                int n = n0 + tid;
                float dj = dinvS[n];
                sS[tid] = dj * (sraw * inv_cnt + dj * x[(bA * Nn + n) * Tn + t]);
            }
            __syncthreads();

            float2 zz[4];
            // ---- z gate ----
            {
                float c0 = sCoef[f0], c1 = sCoef[f0 + 1];
                float d0 = sCoef[64 + f0], d1 = sCoef[64 + f0 + 1];
                float bz0 = sBias[128 + f0], bz1 = sBias[128 + f0 + 1];
                ull acc[4];
#pragma unroll
                for (int jy = 0; jy < 4; jy++) {
                    float s = sS[r0 + jy];
                    acc[jy] = pack2(s * c0 + d0 + bz0, s * c1 + d1 + bz1);
                }
#pragma unroll 4
                for (int ff = 0; ff < 64; ff += 4) {
                    float4 Hq[4];
#pragma unroll
                    for (int jy = 0; jy < 4; jy++) Hq[jy] = *(const float4*)&hS[(r0 + jy) * 64 + ff];
                    const float* Hp = (const float*)Hq;
#pragma unroll
                    for (int s = 0; s < 4; s++) {
                        ull wv = *(const ull*)&sWz[(ff + s) * 64 + f0];
#pragma unroll
                        for (int jy = 0; jy < 4; jy++) fma2(acc[jy], splat2(Hp[jy * 4 + s]), wv);
                    }
                }
#pragma unroll
                for (int jy = 0; jy < 4; jy++) {
                    float2 a = unpack2(acc[jy]);
                    zz[jy] = make_float2(1.0f / (1.0f + expf(-a.x)), 1.0f / (1.0f + expf(-a.y)));
                }
            }
            // ---- r gate -> hrS ----
            {
                float c0 = sCoef[128 + f0], c1 = sCoef[128 + f0 + 1];
                float d0 = sCoef[192 + f0], d1 = sCoef[192 + f0 + 1];
                float br0 = sBias[192 + f0], br1 = sBias[192 + f0 + 1];
                ull acc[4];
#pragma unroll
                for (int jy = 0; jy < 4; jy++) {
                    float s = sS[r0 + jy];
                    acc[jy] = pack2(s * c0 + d0 + br0, s * c1 + d1 + br1);
                }
#pragma unroll 4
                for (int ff = 0; ff < 64; ff += 4) {
                    float4 Hq[4];
#pragma unroll
                    for (int jy = 0; jy < 4; jy++) Hq[jy] = *(const float4*)&hS[(r0 + jy) * 64 + ff];
                    const float* Hp = (const float*)Hq;
#pragma unroll
                    for (int s = 0; s < 4; s++) {
                        ull wv = *(const ull*)&sWr[(ff + s) * 64 + f0];
#pragma unroll
                        for (int jy = 0; jy < 4; jy++) fma2(acc[jy], splat2(Hp[jy * 4 + s]), wv);
                    }
                }
#pragma unroll
                for (int jy = 0; jy < 4; jy++) {
                    float2 a = unpack2(acc[jy]);
                    float rv0 = 1.0f / (1.0f + expf(-a.x));
                    float rv1 = 1.0f / (1.0f + expf(-a.y));
                    float2 hv = *(const float2*)&hS[(r0 + jy) * 64 + f0];
                    *(float2*)&hrS[(r0 + jy) * 64 + f0] = make_float2(hv.x * rv0, hv.y * rv1);
                }
            }
            __syncwarp();
            // ---- h candidate + combine ----
            {
                float c0 = sCoef[256 + f0], c1 = sCoef[256 + f0 + 1];
                float d0 = sCoef[320 + f0], d1 = sCoef[320 + f0 + 1];
                float bh0 = sBias[256 + f0], bh1 = sBias[256 + f0 + 1];
                ull acc[4];
#pragma unroll
                for (int jy = 0; jy < 4; jy++) {
                    float s = sS[r0 + jy];
                    acc[jy] = pack2(s * c0 + d0 + bh0, s * c1 + d1 + bh1);
                }
#pragma unroll 4
                for (int ff = 0; ff < 64; ff += 4) {
                    float4 Hq[4];
#pragma unroll
                    for (int jy = 0; jy < 4; jy++) Hq[jy] = *(const float4*)&hrS[(r0 + jy) * 64 + ff];
                    const float* Hp = (const float*)Hq;
#pragma unroll
                    for (int s = 0; s < 4; s++) {
                        ull wv = *(const ull*)&sWh[(ff + s) * 64 + f0];
#pragma unroll
                        for (int jy = 0; jy < 4; jy++) fma2(acc[jy], splat2(Hp[jy * 4 + s]), wv);
                    }
                }
                __syncwarp();
#pragma unroll
                for (int jy = 0; jy < 4; jy++) {
                    float2 a = unpack2(acc[jy]);
                    float ht0 = tanhf(a.x);
                    float ht1 = tanhf(a.y);
                    float2 hv = *(const float2*)&hS[(r0 + jy) * 64 + f0];
                    float hn0 = zz[jy].x * hv.x + (1.0f - zz[jy].x) * ht0;
                    float hn1 = zz[jy].y * hv.y + (1.0f - zz[jy].y) * ht1;
                    *(float2*)&hS[(r0 + jy) * 64 + f0] = make_float2(hn0, hn1);
                    if (t == Tn - 1)
                        *(float2*)&g_h[(bA * Nn + n0 + r0 + jy) * Hn + f0] = make_float2(hn0, hn1);
                }
            }
            // ---- next-step XW ----
            if (t < Tn - 1) {
                __syncthreads();
                ull acc[4] = {0ull, 0ull, 0ull, 0ull};
#pragma unroll
                for (int c = 0; c < Wn; c++) {
                    ull wv = *(const ull*)&sWg[c * 64 + f0];
#pragma unroll
                    for (int jy = 0; jy < 4; jy++) fma2(acc[jy], splat2(sIt[(r0 + jy) * 12 + c]), wv);
                }
#pragma unroll 4
                for (int c = 0; c < Hn; c++) {
                    ull wv = *(const ull*)&sWg[(Wn + c) * 64 + f0];
#pragma unroll
                    for (int jy = 0; jy < 4; jy++) fma2(acc[jy], splat2(hS[(r0 + jy) * 64 + c]), wv);
                }
#pragma unroll
                for (int jy = 0; jy < 4; jy++)
                    *(float2*)&g_XW[(bA * Nn + n0 + r0 + jy) * EDn + f0] = unpack2(acc[jy]);
            }
        }
        gsync_b(grp, lgen);
    }
}

// ---------------- final classifier ----------------
__global__ __launch_bounds__(256) void k_cls(const float* __restrict__ cls_w,
                                             const float* __restrict__ cls_b,
                                             float* __restrict__ out) {
    int b = blockIdx.x, tid = threadIdx.x;
    float acc[4] = {0.f, 0.f, 0.f, 0.f};
    for (int i = tid; i < Nn * Hn; i += 256) {
        float hv = g_h[b * Nn * Hn + i];
#pragma unroll
        for (int c = 0; c < 4; c++) acc[c] += hv * cls_w[i * Cn + c];
    }
    __shared__ float red[4][256];
#pragma unroll
    for (int c = 0; c < 4; c++) red[c][tid] = acc[c];
    __syncthreads();
    for (int s = 128; s > 0; s >>= 1) {
        if (tid < s) {
#pragma unroll
            for (int c = 0; c < 4; c++) red[c][tid] += red[c][tid + s];
        }
        __syncthreads();
    }
    if (tid < 4) out[b * Cn + tid] = red[tid][0] + cls_b[tid];
}

// ---------------- launch ----------------
extern "C" void kernel_launch(void* const* d_in, const int* in_sizes, int n_in,
                              void* d_out, int out_size) {
    const float* x        = (const float*)d_in[0];
    const float* ew       = (const float*)d_in[1];
    const float* gconv_w  = (const float*)d_in[2];
    const float* gconv_b  = (const float*)d_in[3];
    const float* w1       = (const float*)d_in[4];
    const float* b1       = (const float*)d_in[5];
    const float* w2       = (const float*)d_in[6];
    const float* b2       = (const float*)d_in[7];
    const float* wz_c     = (const float*)d_in[8];
    const float* bz_c     = (const float*)d_in[9];
    const float* wz_l     = (const float*)d_in[10];
    const float* bz_l     = (const float*)d_in[11];
    const float* wr_c     = (const float*)d_in[12];
    const float* br_c     = (const float*)d_in[13];
    const float* wr_l     = (const float*)d_in[14];
    const float* br_l     = (const float*)d_in[15];
    const float* wh_c     = (const float*)d_in[16];
    const float* bh_c     = (const float*)d_in[17];
    const float* wh_l     = (const float*)d_in[18];
    const float* bh_l     = (const float*)d_in[19];
    const float* cls_w    = (const float*)d_in[20];
    const float* cls_b    = (const float*)d_in[21];
    const int*   eidx     = (const int*)d_in[22];
    float* out = (float*)d_out;

    static int smem_set = 0;
    if (!smem_set) {
        cudaFuncSetAttribute(k_persist, cudaFuncAttributeMaxDynamicSharedMemorySize, SMEM_BYTES);
        smem_set = 1;
    }

    k_zero<<<2048, 256>>>();
    k_build<<<1, 256>>>(eidx, ew);
    k_precoef<<<1, 64>>>(wz_c, wz_l, bz_c, wr_c, wr_l, br_c, wh_c, wh_l, bh_c);
    k_persist<<<NBLK, 256, SMEM_BYTES>>>(x, gconv_w, gconv_b, w1, b1, w2, b2,
                                         bz_l, wz_l, br_l, wr_l, bh_l, wh_l);
    k_cls<<<Bn, 256>>>(cls_w, cls_b, out);
}

// round 11
// speedup vs baseline: 2.0529x; 1.0482x over previous
#include <cuda_runtime.h>
#include <math.h>

#define Bn 16
#define Nn 256
#define Tn 64
#define Wn 12
#define Hn 64
#define EDn 64
#define Sn 5
#define Cn 4
#define En 2048
#define FGn 76   // W + H
#define CAP 64
#define GBLK 9            // blocks per batch group
#define NBLK (Bn * GBLK)  // 144
#define NT 512            // threads per block

typedef unsigned long long ull;

// ---------------- f32x2 packed-FMA helpers (sm_103a FFMA2) ----------------
__device__ __forceinline__ void fma2(ull& d, ull a, ull b) {
    asm("fma.rn.f32x2 %0, %1, %2, %0;" : "+l"(d) : "l"(a), "l"(b));
}
__device__ __forceinline__ ull splat2(float v) {
    ull r; asm("mov.b64 %0, {%1, %1};" : "=l"(r) : "f"(v)); return r;
}
__device__ __forceinline__ ull pack2(float lo, float hi) {
    ull r; asm("mov.b64 %0, {%1, %2};" : "=l"(r) : "f"(lo), "f"(hi)); return r;
}
__device__ __forceinline__ float2 unpack2(ull v) {
    float lo, hi; asm("mov.b64 {%0, %1}, %2;" : "=f"(lo), "=f"(hi) : "l"(v));
    return make_float2(lo, hi);
}
__device__ __forceinline__ float hadd2(ull v) { float2 f = unpack2(v); return f.x + f.y; }

// triangular pair LUT (36 pairs of 8x8 tiles)
__device__ __constant__ signed char c_iT[36] =
    {0,0,0,0,0,0,0,0, 1,1,1,1,1,1,1, 2,2,2,2,2,2, 3,3,3,3,3, 4,4,4,4, 5,5,5, 6,6, 7};
__device__ __constant__ signed char c_jT[36] =
    {0,1,2,3,4,5,6,7, 1,2,3,4,5,6,7, 2,3,4,5,6,7, 3,4,5,6,7, 4,5,6,7, 5,6,7, 6,7, 7};

// ---------------- device scratch ----------------
__device__ float g_dinv_stat[Nn];
__device__ int   g_nbr_cnt[Nn];
__device__ int   g_nbr_idx[Nn * CAP];
__device__ float g_nbr_w[Nn * CAP];
__device__ float g_coef[6 * Hn];
__device__ float g_XW[Bn * Nn * EDn];
__device__ float g_de1[Bn * Nn * EDn];
__device__ float g_de2[Bn * Nn * EDn];
__device__ float g_Eh[(size_t)Bn * Sn * Nn * Nn];
__device__ float g_Msum[(size_t)Bn * Nn * Nn];
__device__ float g_colsum[Bn * Nn];
__device__ float g_h[Bn * Nn * Hn];
__device__ unsigned g_bcount[Bn * 32];
__device__ unsigned g_bgen[Bn * 32];

// ---------------- smem layout (floats) ----------------
#define OFF_W1   0
#define OFF_W2   4096
#define OFF_WZ   8192
#define OFF_WR   12288
#define OFF_WH   16384
#define OFF_WG   20480          // 4864
#define OFF_COEF 25344          // 384
#define OFF_BIAS 25728          // 384: [b1,b2,bz,br,bh,gconv_b]
#define OFF_H    26112          // 2048 persistent h rows
#define OFF_NBRW 28160          // 2048
#define OFF_NBRI 30208          // 2048 (int view)
#define OFF_NBRC 32256          // 32 (int view)
#define OFF_WK   32288          // 9824 work area
#define SMEM_FLOATS (OFF_WK + 9824)
#define SMEM_BYTES (SMEM_FLOATS * 4)

// ---------------- per-batch grid barrier (9 arrivals) ----------------
__device__ __forceinline__ void gsync_b(int grp, unsigned& lgen) {
    __syncthreads();
    if (threadIdx.x == 0) {
        unsigned* cnt = &g_bcount[grp * 32];
        unsigned* gen = &g_bgen[grp * 32];
        __threadfence();
        if (atomicAdd(cnt, 1u) == (unsigned)(GBLK - 1)) {
            *cnt = 0u;
            __threadfence();
            atomicAdd(gen, 1u);
        } else {
            while (atomicAdd(gen, 0u) <= lgen) { __nanosleep(20); }
        }
        __threadfence();
    }
    lgen++;
    __syncthreads();
}

// ---------------- setup kernels ----------------
__global__ void k_zero() {
    size_t idx = (size_t)blockIdx.x * blockDim.x + threadIdx.x;
    size_t str = (size_t)gridDim.x * blockDim.x;
    if (idx < Bn * 32) { g_bcount[idx] = 0u; g_bgen[idx] = 0u; }
    for (size_t i = idx; i < (size_t)Bn * Sn * Nn * Nn; i += str) g_Eh[i] = 0.f;
    for (size_t i = idx; i < (size_t)Bn * Nn * Nn; i += str) g_Msum[i] = 0.f;
    for (size_t i = idx; i < (size_t)Bn * Nn; i += str) g_colsum[i] = 0.f;
}

__global__ void k_build(const int* __restrict__ ei, const float* __restrict__ ew) {
    int j = threadIdx.x;  // 256 threads, 1 block
    float deg = 1.0f;
    for (int e = 0; e < En; e++)
        if (ei[En + e] == j) deg += ew[e];
    g_dinv_stat[j] = 1.0f / sqrtf(deg);
    __syncthreads();
    float dj = g_dinv_stat[j];
    int cnt = 1;
    g_nbr_idx[j * CAP] = j;
    g_nbr_w[j * CAP] = dj * dj;
    for (int e = 0; e < En; e++) {
        if (ei[En + e] == j && cnt < CAP) {
            int s = ei[e];
            g_nbr_idx[j * CAP + cnt] = s;
            g_nbr_w[j * CAP + cnt] = g_dinv_stat[s] * ew[e] * dj;
            cnt++;
        }
    }
    g_nbr_cnt[j] = cnt;
}

__global__ void k_precoef(const float* wz_c, const float* wz_l, const float* bz_c,
                          const float* wr_c, const float* wr_l, const float* br_c,
                          const float* wh_c, const float* wh_l, const float* bh_c) {
    int k = threadIdx.x;  // 64 threads
    float az = 0, cz = 0, ar = 0, cr = 0, ah = 0, ch = 0;
    for (int f = 0; f < Hn; f++) {
        float wzl = wz_l[f * Hn + k], wrl = wr_l[f * Hn + k], whl = wh_l[f * Hn + k];
        az += wz_c[f] * wzl;  cz += bz_c[f] * wzl;
        ar += wr_c[f] * wrl;  cr += br_c[f] * wrl;
        ah += wh_c[f] * whl;  ch += bh_c[f] * whl;
    }
    g_coef[k] = az;        g_coef[64 + k] = cz;
    g_coef[128 + k] = ar;  g_coef[192 + k] = cr;
    g_coef[256 + k] = ah;  g_coef[320 + k] = ch;
}

// ---------------- persistent kernel: whole T-step scan ----------------
__global__ __launch_bounds__(NT, 1) void k_persist(
    const float* __restrict__ x, const float* __restrict__ Wg,
    const float* __restrict__ gconv_b,
    const float* __restrict__ w1, const float* __restrict__ b1,
    const float* __restrict__ w2, const float* __restrict__ b2,
    const float* __restrict__ bz_lf, const float* __restrict__ wz_l,
    const float* __restrict__ br_lf, const float* __restrict__ wr_l,
    const float* __restrict__ bh_lf, const float* __restrict__ wh_l)
{
    extern __shared__ float sm[];
    int tid = threadIdx.x, bid = blockIdx.x;
    int grp = bid / GBLK;          // batch
    int role = bid - grp * GBLK;   // 0..8
    int bA = grp, nT = role;
    bool ac_on = (role < 8);
    unsigned lgen = 0;

    float* sW1 = sm + OFF_W1;
    float* sW2 = sm + OFF_W2;
    float* sWz = sm + OFF_WZ;
    float* sWr = sm + OFF_WR;
    float* sWh = sm + OFF_WH;
    float* sWg = sm + OFF_WG;
    float* sCoef = sm + OFF_COEF;
    float* sBias = sm + OFF_BIAS;
    float* hS = sm + OFF_H;
    float* sNbrW = sm + OFF_NBRW;
    int* sNbrI = (int*)(sm + OFF_NBRI);
    int* sNbrC = (int*)(sm + OFF_NBRC);
    float* wk = sm + OFF_WK;

    // ---- load all weights once ----
    for (int i = tid; i < 4096; i += NT) {
        sW1[i] = w1[i];
        sW2[i] = w2[i];
        int r = i >> 6, c = i & 63;
        sWz[i] = wz_l[(64 + r) * 64 + c];
        sWr[i] = wr_l[(64 + r) * 64 + c];
        sWh[i] = wh_l[(64 + r) * 64 + c];
    }
    for (int i = tid; i < FGn * 64; i += NT) sWg[i] = Wg[i];
    for (int i = tid; i < 384; i += NT) sCoef[i] = g_coef[i];
    if (tid < 64) {
        sBias[tid] = b1[tid];        sBias[64 + tid] = b2[tid];
        sBias[128 + tid] = bz_lf[tid]; sBias[192 + tid] = br_lf[tid];
        sBias[256 + tid] = bh_lf[tid]; sBias[320 + tid] = gconv_b[tid];
    }
    for (int i = tid; i < 2048; i += NT) hS[i] = 0.f;

    if (ac_on) {
        for (int i = tid; i < 32 * CAP; i += NT) {
            sNbrI[i] = g_nbr_idx[nT * 32 * CAP + i];
            sNbrW[i] = g_nbr_w[nT * 32 * CAP + i];
        }
        if (tid < 32) sNbrC[tid] = g_nbr_cnt[nT * 32 + tid];
    }
    __syncthreads();

    int tx = tid & 31, ty = tid >> 5;   // ty 0..15
    int f0 = tx * 2, r0 = ty * 2;       // 2-row register tiles

    // ---- initial XW (t=0, h=0) ----
    if (ac_on) {
        float* sIt = wk;  // [32][12]
        for (int i = tid; i < 384; i += NT) {
            int rr = i / 12, c = i - rr * 12;
            int tt = c - (Wn - 1);
            sIt[i] = (tt >= 0) ? x[(bA * Nn + nT * 32 + rr) * Tn + tt] : 0.f;
        }
        __syncthreads();
        ull acc[2] = {0ull, 0ull};
#pragma unroll
        for (int c = 0; c < Wn; c++) {
            ull wv = *(const ull*)&sWg[c * 64 + f0];
#pragma unroll
            for (int jy = 0; jy < 2; jy++) fma2(acc[jy], splat2(sIt[(r0 + jy) * 12 + c]), wv);
        }
#pragma unroll
        for (int jy = 0; jy < 2; jy++)
            *(float2*)&g_XW[(bA * Nn + nT * 32 + r0 + jy) * EDn + f0] = unpack2(acc[jy]);
    }
    gsync_b(grp, lgen);

    for (int t = 0; t < Tn; t++) {
        int slot = t % Sn;
        float cnt = (float)((t + 1 < Sn) ? (t + 1) : Sn);

        // ================= phase A: df gather + de1/de2 =================
        if (ac_on) {
            float* dfS = wk;  // [32][64]
            {
                int f = tid & 63, jg = tid >> 6;   // jg 0..7
                float gb = sBias[320 + f];
#pragma unroll
                for (int q = 0; q < 4; q++) {
                    int jl = jg + q * 8;
                    int nc = sNbrC[jl];
                    float acc = 0.f;
                    for (int k = 0; k < nc; k++)
                        acc += sNbrW[jl * CAP + k] * g_XW[(bA * Nn + sNbrI[jl * CAP + k]) * EDn + f];
                    dfS[jl * 64 + f] = acc + gb;
                }
            }
            __syncthreads();
            ull a1[2], a2[2];
#pragma unroll
            for (int jy = 0; jy < 2; jy++) { a1[jy] = 0ull; a2[jy] = 0ull; }
#pragma unroll 4
            for (int ff = 0; ff < 64; ff += 4) {
                float4 D[2];
#pragma unroll
                for (int jy = 0; jy < 2; jy++) D[jy] = *(const float4*)&dfS[(r0 + jy) * 64 + ff];
                const float* Dp = (const float*)D;
#pragma unroll
                for (int s = 0; s < 4; s++) {
                    ull w1v = *(const ull*)&sW1[(ff + s) * 64 + f0];
                    ull w2v = *(const ull*)&sW2[(ff + s) * 64 + f0];
#pragma unroll
                    for (int jy = 0; jy < 2; jy++) {
                        ull dv = splat2(Dp[jy * 4 + s]);
                        fma2(a1[jy], dv, w1v);
                        fma2(a2[jy], dv, w2v);
                    }
                }
            }
            {
                float bb10 = sBias[f0], bb11 = sBias[f0 + 1];
                float bb20 = sBias[64 + f0], bb21 = sBias[64 + f0 + 1];
#pragma unroll
                for (int jy = 0; jy < 2; jy++) {
                    int row = (bA * Nn + nT * 32 + r0 + jy) * EDn;
                    float2 v1 = unpack2(a1[jy]);
                    float2 v2 = unpack2(a2[jy]);
                    *(float2*)&g_de1[row + f0] = make_float2(tanhf(v1.x + bb10), tanhf(v1.y + bb11));
                    *(float2*)&g_de2[row + f0] = make_float2(tanhf(v2.x + bb20), tanhf(v2.y + bb21));
                }
            }
        }
        gsync_b(grp, lgen);

        // ================= phase B: Et tiles (4 per block, own batch) =================
        {
            float* d1i = wk;
            float* d2i = wk + 2176;
            float* d1j = wk + 4352;
            float* d2j = wk + 6528;
            float* tS  = wk + 8704;   // stride 33
            float* colbuf = wk + 9760;
            int bx = tid & 15, by = tid >> 4;   // by = ii (0..31); jj = bx + 16c
#pragma unroll 1
            for (int k4 = 0; k4 < 4; k4++) {
                int u = role * 4 + k4;
                if (u >= 36) break;
                int iT = c_iT[u], jT = c_jT[u];
                bool diag = (iT == jT);
                int bb = bA;

                for (int i = tid; i < 512; i += NT) {
                    int rr = i >> 4, e = (i & 15) * 4;
                    int gi = (bb * Nn + iT * 32 + rr) * EDn + e;
                    int gj = (bb * Nn + jT * 32 + rr) * EDn + e;
                    *(float4*)&d1i[rr * 68 + e] = *(const float4*)&g_de1[gi];
                    *(float4*)&d2i[rr * 68 + e] = *(const float4*)&g_de2[gi];
                    *(float4*)&d1j[rr * 68 + e] = *(const float4*)&g_de1[gj];
                    *(float4*)&d2j[rr * 68 + e] = *(const float4*)&g_de2[gj];
                }
                if (tid < 64) colbuf[tid] = 0.f;
                __syncthreads();

                ull accA[2], accB[2];
#pragma unroll
                for (int c = 0; c < 2; c++) { accA[c] = 0ull; accB[c] = 0ull; }
#pragma unroll
                for (int e0 = 0; e0 < 64; e0 += 4) {
                    ulonglong2 P1 = *(const ulonglong2*)&d1i[by * 68 + e0];
                    ulonglong2 P2 = *(const ulonglong2*)&d2i[by * 68 + e0];
#pragma unroll
                    for (int c = 0; c < 2; c++) {
                        ulonglong2 Q1 = *(const ulonglong2*)&d1j[(bx + 16 * c) * 68 + e0];
                        ulonglong2 Q2 = *(const ulonglong2*)&d2j[(bx + 16 * c) * 68 + e0];
                        fma2(accA[c], P1.x, Q2.x);  fma2(accA[c], P1.y, Q2.y);
                        fma2(accB[c], Q1.x, P2.x);  fma2(accB[c], Q1.y, P2.y);
                    }
                }
                float tv[2];
#pragma unroll
                for (int c = 0; c < 2; c++) {
                    tv[c] = tanhf(hadd2(accA[c]) - hadd2(accB[c]));
                    tS[by * 33 + bx + 16 * c] = tv[c];
                }
                __syncthreads();

                size_t ebase = ((size_t)(bb * Sn + slot) * Nn) * Nn;
                size_t mbase = ((size_t)bb * Nn) * Nn;
#pragma unroll
                for (int q = 0; q < 2; q++) {
                    int idx = tid + q * NT;
                    int ii = idx >> 5, jj = idx & 31;
                    float et = fmaxf(tS[ii * 33 + jj], 0.f);
                    size_t eo = ebase + (size_t)(iT * 32 + ii) * Nn + jT * 32 + jj;
                    float old = g_Eh[eo];
                    g_Eh[eo] = et;
                    float d = et - old;
                    g_Msum[mbase + (size_t)(iT * 32 + ii) * Nn + jT * 32 + jj] += d;
                    atomicAdd(&colbuf[jj], d);
                }
                if (!diag) {
                    __syncthreads();
#pragma unroll
                    for (int c = 0; c < 2; c++)
                        tS[(bx + 16 * c) * 33 + by] = fmaxf(-tv[c], 0.f);
                    __syncthreads();
#pragma unroll
                    for (int q = 0; q < 2; q++) {
                        int idx = tid + q * NT;
                        int rr = idx >> 5, cc = idx & 31;
                        float et = tS[rr * 33 + cc];
                        size_t eo = ebase + (size_t)(jT * 32 + rr) * Nn + iT * 32 + cc;
                        float old = g_Eh[eo];
                        g_Eh[eo] = et;
                        float d = et - old;
                        g_Msum[mbase + (size_t)(jT * 32 + rr) * Nn + iT * 32 + cc] += d;
                        atomicAdd(&colbuf[32 + cc], d);
                    }
                }
                __syncthreads();
                if (tid < 32) atomicAdd(&g_colsum[bb * Nn + jT * 32 + tid], colbuf[tid]);
                if (!diag && tid >= 32 && tid < 64)
                    atomicAdd(&g_colsum[bb * Nn + iT * 32 + (tid - 32)], colbuf[tid]);
                __syncthreads();
            }
        }
        gsync_b(grp, lgen);

        // ================= phase C: s-reduction + GRU + next XW =================
        if (ac_on) {
            int n0 = nT * 32;
            float* hrS   = wk;          // [32][64]
            float* dinvS = wk + 2048;   // 256
            float* dxvS  = wk + 2304;   // 256
            float* part  = wk + 2560;   // 512
            float* sS    = wk + 3072;   // 32
            float* sIt   = wk + 3104;   // [32][12]
            float inv_cnt = 1.0f / cnt;

            if (tid < 256) {
                int i = tid;
                float cs = g_colsum[bA * Nn + i];
                float dv = 1.0f / sqrtf(cs * inv_cnt + 1.0f);
                dinvS[i] = dv;
                dxvS[i] = dv * x[(bA * Nn + i) * Tn + t];
            }
            if (t < Tn - 1) {
                for (int i = tid; i < 384; i += NT) {
                    int rr = i / 12, c = i - rr * 12;
                    int tt = t + 1 + c - (Wn - 1);
                    sIt[i] = (tt >= 0) ? x[(bA * Nn + n0 + rr) * Tn + tt] : 0.f;
                }
            }
            __syncthreads();
            {
                int c = tid & 31, g = tid >> 5;   // 16 groups of 16 i's
                float acc = 0.f;
                int ibase = g * 16;
#pragma unroll 8
                for (int k = 0; k < 16; k++) {
                    int i = ibase + k;
                    acc += g_Msum[((size_t)bA * Nn + i) * Nn + n0 + c] * dxvS[i];
                }
                part[g * 32 + c] = acc;
            }
            __syncthreads();
            if (tid < 32) {
                float sraw = 0.f;
#pragma unroll
                for (int g = 0; g < 16; g++) sraw += part[g * 32 + tid];
                int n = n0 + tid;
                float dj = dinvS[n];
                sS[tid] = dj * (sraw * inv_cnt + dj * x[(bA * Nn + n) * Tn + t]);
            }
            __syncthreads();

            float2 zz[2];
            // ---- z gate ----
            {
                float c0 = sCoef[f0], c1 = sCoef[f0 + 1];
                float d0 = sCoef[64 + f0], d1 = sCoef[64 + f0 + 1];
                float bz0 = sBias[128 + f0], bz1 = sBias[128 + f0 + 1];
                ull acc[2];
#pragma unroll
                for (int jy = 0; jy < 2; jy++) {
                    float s = sS[r0 + jy];
                    acc[jy] = pack2(s * c0 + d0 + bz0, s * c1 + d1 + bz1);
                }
#pragma unroll 4
                for (int ff = 0; ff < 64; ff += 4) {
                    float4 Hq[2];
#pragma unroll
                    for (int jy = 0; jy < 2; jy++) Hq[jy] = *(const float4*)&hS[(r0 + jy) * 64 + ff];
                    const float* Hp = (const float*)Hq;
#pragma unroll
                    for (int s = 0; s < 4; s++) {
                        ull wv = *(const ull*)&sWz[(ff + s) * 64 + f0];
#pragma unroll
                        for (int jy = 0; jy < 2; jy++) fma2(acc[jy], splat2(Hp[jy * 4 + s]), wv);
                    }
                }
#pragma unroll
                for (int jy = 0; jy < 2; jy++) {
                    float2 a = unpack2(acc[jy]);
                    zz[jy] = make_float2(1.0f / (1.0f + expf(-a.x)), 1.0f / (1.0f + expf(-a.y)));
                }
            }
            // ---- r gate -> hrS ----
            {
                float c0 = sCoef[128 + f0], c1 = sCoef[128 + f0 + 1];
                float d0 = sCoef[192 + f0], d1 = sCoef[192 + f0 + 1];
                float br0 = sBias[192 + f0], br1 = sBias[192 + f0 + 1];
                ull acc[2];
#pragma unroll
                for (int jy = 0; jy < 2; jy++) {
                    float s = sS[r0 + jy];
                    acc[jy] = pack2(s * c0 + d0 + br0, s * c1 + d1 + br1);
                }
#pragma unroll 4
                for (int ff = 0; ff < 64; ff += 4) {
                    float4 Hq[2];
#pragma unroll
                    for (int jy = 0; jy < 2; jy++) Hq[jy] = *(const float4*)&hS[(r0 + jy) * 64 + ff];
                    const float* Hp = (const float*)Hq;
#pragma unroll
                    for (int s = 0; s < 4; s++) {
                        ull wv = *(const ull*)&sWr[(ff + s) * 64 + f0];
#pragma unroll
                        for (int jy = 0; jy < 2; jy++) fma2(acc[jy], splat2(Hp[jy * 4 + s]), wv);
                    }
                }
#pragma unroll
                for (int jy = 0; jy < 2; jy++) {
                    float2 a = unpack2(acc[jy]);
                    float rv0 = 1.0f / (1.0f + expf(-a.x));
                    float rv1 = 1.0f / (1.0f + expf(-a.y));
                    float2 hv = *(const float2*)&hS[(r0 + jy) * 64 + f0];
                    *(float2*)&hrS[(r0 + jy) * 64 + f0] = make_float2(hv.x * rv0, hv.y * rv1);
                }
            }
            __syncwarp();
            // ---- h candidate + combine (rows r0..r0+1 are warp-private) ----
            {
                float c0 = sCoef[256 + f0], c1 = sCoef[256 + f0 + 1];
                float d0 = sCoef[320 + f0], d1 = sCoef[320 + f0 + 1];
                float bh0 = sBias[256 + f0], bh1 = sBias[256 + f0 + 1];
                ull acc[2];
#pragma unroll
                for (int jy = 0; jy < 2; jy++) {
                    float s = sS[r0 + jy];
                    acc[jy] = pack2(s * c0 + d0 + bh0, s * c1 + d1 + bh1);
                }
#pragma unroll 4
                for (int ff = 0; ff < 64; ff += 4) {
                    float4 Hq[2];
#pragma unroll
                    for (int jy = 0; jy < 2; jy++) Hq[jy] = *(const float4*)&hrS[(r0 + jy) * 64 + ff];
                    const float* Hp = (const float*)Hq;
#pragma unroll
                    for (int s = 0; s < 4; s++) {
                        ull wv = *(const ull*)&sWh[(ff + s) * 64 + f0];
#pragma unroll
                        for (int jy = 0; jy < 2; jy++) fma2(acc[jy], splat2(Hp[jy * 4 + s]), wv);
                    }
                }
                __syncwarp();
#pragma unroll
                for (int jy = 0; jy < 2; jy++) {
                    float2 a = unpack2(acc[jy]);
                    float ht0 = tanhf(a.x);
                    float ht1 = tanhf(a.y);
                    float2 hv = *(const float2*)&hS[(r0 + jy) * 64 + f0];
                    float hn0 = zz[jy].x * hv.x + (1.0f - zz[jy].x) * ht0;
                    float hn1 = zz[jy].y * hv.y + (1.0f - zz[jy].y) * ht1;
                    *(float2*)&hS[(r0 + jy) * 64 + f0] = make_float2(hn0, hn1);
                    if (t == Tn - 1)
                        *(float2*)&g_h[(bA * Nn + n0 + r0 + jy) * Hn + f0] = make_float2(hn0, hn1);
                }
            }
            // ---- next-step XW ----
            if (t < Tn - 1) {
                __syncthreads();
                ull acc[2] = {0ull, 0ull};
#pragma unroll
                for (int c = 0; c < Wn; c++) {
                    ull wv = *(const ull*)&sWg[c * 64 + f0];
#pragma unroll
                    for (int jy = 0; jy < 2; jy++) fma2(acc[jy], splat2(sIt[(r0 + jy) * 12 + c]), wv);
                }
#pragma unroll 4
                for (int c = 0; c < Hn; c++) {
                    ull wv = *(const ull*)&sWg[(Wn + c) * 64 + f0];
#pragma unroll
                    for (int jy = 0; jy < 2; jy++) fma2(acc[jy], splat2(hS[(r0 + jy) * 64 + c]), wv);
                }
#pragma unroll
                for (int jy = 0; jy < 2; jy++)
                    *(float2*)&g_XW[(bA * Nn + n0 + r0 + jy) * EDn + f0] = unpack2(acc[jy]);
            }
        }
        gsync_b(grp, lgen);
    }
}

// ---------------- final classifier ----------------
__global__ __launch_bounds__(256) void k_cls(const float* __restrict__ cls_w,
                                             const float* __restrict__ cls_b,
                                             float* __restrict__ out) {
    int b = blockIdx.x, tid = threadIdx.x;
    float acc[4] = {0.f, 0.f, 0.f, 0.f};
    for (int i = tid; i < Nn * Hn; i += 256) {
        float hv = g_h[b * Nn * Hn + i];
#pragma unroll
        for (int c = 0; c < 4; c++) acc[c] += hv * cls_w[i * Cn + c];
    }
    __shared__ float red[4][256];
#pragma unroll
    for (int c = 0; c < 4; c++) red[c][tid] = acc[c];
    __syncthreads();
    for (int s = 128; s > 0; s >>= 1) {
        if (tid < s) {
#pragma unroll
            for (int c = 0; c < 4; c++) red[c][tid] += red[c][tid + s];
        }
        __syncthreads();
    }
    if (tid < 4) out[b * Cn + tid] = red[tid][0] + cls_b[tid];
}

// ---------------- launch ----------------
extern "C" void kernel_launch(void* const* d_in, const int* in_sizes, int n_in,
                              void* d_out, int out_size) {
    const float* x        = (const float*)d_in[0];
    const float* ew       = (const float*)d_in[1];
    const float* gconv_w  = (const float*)d_in[2];
    const float* gconv_b  = (const float*)d_in[3];
    const float* w1       = (const float*)d_in[4];
    const float* b1       = (const float*)d_in[5];
    const float* w2       = (const float*)d_in[6];
    const float* b2       = (const float*)d_in[7];
    const float* wz_c     = (const float*)d_in[8];
    const float* bz_c     = (const float*)d_in[9];
    const float* wz_l     = (const float*)d_in[10];
    const float* bz_l     = (const float*)d_in[11];
    const float* wr_c     = (const float*)d_in[12];
    const float* br_c     = (const float*)d_in[13];
    const float* wr_l     = (const float*)d_in[14];
    const float* br_l     = (const float*)d_in[15];
    const float* wh_c     = (const float*)d_in[16];
    const float* bh_c     = (const float*)d_in[17];
    const float* wh_l     = (const float*)d_in[18];
    const float* bh_l     = (const float*)d_in[19];
    const float* cls_w    = (const float*)d_in[20];
    const float* cls_b    = (const float*)d_in[21];
    const int*   eidx     = (const int*)d_in[22];
    float* out = (float*)d_out;

    static int smem_set = 0;
    if (!smem_set) {
        cudaFuncSetAttribute(k_persist, cudaFuncAttributeMaxDynamicSharedMemorySize, SMEM_BYTES);
        smem_set = 1;
    }

    k_zero<<<2048, 256>>>();
    k_build<<<1, 256>>>(eidx, ew);
    k_precoef<<<1, 64>>>(wz_c, wz_l, bz_c, wr_c, wr_l, br_c, wh_c, wh_l, bh_c);
    k_persist<<<NBLK, NT, SMEM_BYTES>>>(x, gconv_w, gconv_b, w1, b1, w2, b2,
                                        bz_l, wz_l, br_l, wr_l, bh_l, wh_l);
    k_cls<<<Bn, 256>>>(cls_w, cls_b, out);
}